// round 12
// baseline (speedup 1.0000x reference)
#include <cuda_runtime.h>
#include <cuda_bf16.h>
#include <math.h>
#include <stdint.h>

// Problem constants
#define S_LEN 2048
#define DMODEL 2048
#define NHEADS 16
#define DKH 128
#define BATCH 2
#define MROWS (BATCH * S_LEN)   // 4096
#define SQRT_DM 45.254833995939045f

// ---------------------------------------------------------------------------
// Scratch (__device__ globals; no allocation allowed)
// ---------------------------------------------------------------------------
__device__ float g_q[(size_t)MROWS * DMODEL];
__device__ float g_k[(size_t)MROWS * DMODEL];
__device__ float g_v[(size_t)MROWS * DMODEL];
__device__ float g_o[(size_t)MROWS * DMODEL];
__device__ __nv_bfloat16 g_xh[(size_t)MROWS * DMODEL];
__device__ __nv_bfloat16 g_xl[(size_t)MROWS * DMODEL];
__device__ __nv_bfloat16 g_wh[(size_t)DMODEL * DMODEL];
__device__ __nv_bfloat16 g_wl[(size_t)DMODEL * DMODEL];

// ---------------------------------------------------------------------------
// PTX helpers (base sm_100 target safe: mma.sync / ldmatrix / cp.async only)
// ---------------------------------------------------------------------------
static __device__ __forceinline__ uint32_t smem_u32(const void* p) {
    uint32_t a;
    asm("{ .reg .u64 t; cvta.to.shared.u64 t, %1; cvt.u32.u64 %0, t; }"
        : "=r"(a) : "l"(p));
    return a;
}

#define CP_ASYNC16(saddr, gaddr) \
    asm volatile("cp.async.cg.shared.global [%0], [%1], 16;" :: "r"(saddr), "l"(gaddr))
#define CP_ASYNC_COMMIT() asm volatile("cp.async.commit_group;" ::: "memory")
#define CP_ASYNC_WAIT0()  asm volatile("cp.async.wait_group 0;" ::: "memory")
#define CP_ASYNC_WAIT1()  asm volatile("cp.async.wait_group 1;" ::: "memory")

static __device__ __forceinline__ void ldsm_x4(uint32_t (&r)[4], uint32_t addr) {
    asm volatile("ldmatrix.sync.aligned.m8n8.x4.shared.b16 {%0,%1,%2,%3}, [%4];"
                 : "=r"(r[0]), "=r"(r[1]), "=r"(r[2]), "=r"(r[3]) : "r"(addr));
}
static __device__ __forceinline__ void mma_bf16(float (&d)[4],
                                                const uint32_t (&a)[4],
                                                const uint32_t b0, const uint32_t b1) {
    asm volatile("mma.sync.aligned.m16n8k16.row.col.f32.bf16.bf16.f32 "
                 "{%0,%1,%2,%3}, {%4,%5,%6,%7}, {%8,%9}, {%0,%1,%2,%3};"
                 : "+f"(d[0]), "+f"(d[1]), "+f"(d[2]), "+f"(d[3])
                 : "r"(a[0]), "r"(a[1]), "r"(a[2]), "r"(a[3]),
                   "r"(b0), "r"(b1));
}

// ---------------------------------------------------------------------------
// fp32 SIMT GEMM (R1, measured-passing): C = A @ W^T + bias
// Used for the floor-critical Q/K projections. UNCHANGED numerics.
// ---------------------------------------------------------------------------
__global__ __launch_bounds__(256) void gemm_nt_bias(
    const float* __restrict__ A, const float* __restrict__ W,
    const float* __restrict__ bias, float* __restrict__ C)
{
    const int K = DMODEL;
    const int N = DMODEL;

    __shared__ float As[16][132];
    __shared__ float Bs[16][132];

    const int tid = threadIdx.x;
    const int tr  = tid >> 4;
    const int tc  = tid & 15;
    const int bm  = blockIdx.y << 7;
    const int bn  = blockIdx.x << 7;

    const int lr = tid >> 2;
    const int lk = (tid & 3) << 2;

    const float* Ar0 = A + (size_t)(bm + lr) * K + lk;
    const float* Ar1 = A + (size_t)(bm + 64 + lr) * K + lk;
    const float* Wr0 = W + (size_t)(bn + lr) * K + lk;
    const float* Wr1 = W + (size_t)(bn + 64 + lr) * K + lk;

    float acc[8][8];
#pragma unroll
    for (int i = 0; i < 8; i++)
#pragma unroll
        for (int j = 0; j < 8; j++) acc[i][j] = 0.f;

    float4 pa0 = *(const float4*)(Ar0);
    float4 pa1 = *(const float4*)(Ar1);
    float4 pb0 = *(const float4*)(Wr0);
    float4 pb1 = *(const float4*)(Wr1);

    for (int kt = 0; kt < K; kt += 16) {
        As[lk + 0][lr] = pa0.x; As[lk + 1][lr] = pa0.y;
        As[lk + 2][lr] = pa0.z; As[lk + 3][lr] = pa0.w;
        As[lk + 0][64 + lr] = pa1.x; As[lk + 1][64 + lr] = pa1.y;
        As[lk + 2][64 + lr] = pa1.z; As[lk + 3][64 + lr] = pa1.w;
        Bs[lk + 0][lr] = pb0.x; Bs[lk + 1][lr] = pb0.y;
        Bs[lk + 2][lr] = pb0.z; Bs[lk + 3][lr] = pb0.w;
        Bs[lk + 0][64 + lr] = pb1.x; Bs[lk + 1][64 + lr] = pb1.y;
        Bs[lk + 2][64 + lr] = pb1.z; Bs[lk + 3][64 + lr] = pb1.w;
        __syncthreads();

        if (kt + 16 < K) {
            pa0 = *(const float4*)(Ar0 + kt + 16);
            pa1 = *(const float4*)(Ar1 + kt + 16);
            pb0 = *(const float4*)(Wr0 + kt + 16);
            pb1 = *(const float4*)(Wr1 + kt + 16);
        }

#pragma unroll
        for (int k = 0; k < 16; k++) {
            float4 x0 = *(const float4*)&As[k][tr << 2];
            float4 x1 = *(const float4*)&As[k][64 + (tr << 2)];
            float4 y0 = *(const float4*)&Bs[k][tc << 2];
            float4 y1 = *(const float4*)&Bs[k][64 + (tc << 2)];
            float av[8] = {x0.x, x0.y, x0.z, x0.w, x1.x, x1.y, x1.z, x1.w};
            float bv[8] = {y0.x, y0.y, y0.z, y0.w, y1.x, y1.y, y1.z, y1.w};
#pragma unroll
            for (int i = 0; i < 8; i++)
#pragma unroll
                for (int j = 0; j < 8; j++) acc[i][j] += av[i] * bv[j];
        }
        __syncthreads();
    }

#pragma unroll
    for (int i = 0; i < 8; i++) {
        int row = bm + ((i < 4) ? ((tr << 2) + i) : (64 + (tr << 2) + i - 4));
#pragma unroll
        for (int jh = 0; jh < 2; jh++) {
            int col = bn + (jh ? (64 + (tc << 2)) : (tc << 2));
            float4 r;
            r.x = acc[i][jh * 4 + 0] + __ldg(&bias[col + 0]);
            r.y = acc[i][jh * 4 + 1] + __ldg(&bias[col + 1]);
            r.z = acc[i][jh * 4 + 2] + __ldg(&bias[col + 2]);
            r.w = acc[i][jh * 4 + 3] + __ldg(&bias[col + 3]);
            *(float4*)(C + (size_t)row * N + col) = r;
        }
    }
}

// ---------------------------------------------------------------------------
// Split fp32 -> (bf16 hi, bf16 lo); residual exact in fp32.
// ---------------------------------------------------------------------------
__global__ __launch_bounds__(256) void split2_bf16(
    const float* __restrict__ x,
    __nv_bfloat16* __restrict__ h, __nv_bfloat16* __restrict__ l, int n4)
{
    int i = blockIdx.x * blockDim.x + threadIdx.x;
    if (i >= n4) return;
    float4 v = ((const float4*)x)[i];
    float vv[4] = {v.x, v.y, v.z, v.w};
    __nv_bfloat16 hh[4], ll[4];
#pragma unroll
    for (int j = 0; j < 4; j++) {
        hh[j] = __float2bfloat16(vv[j]);
        ll[j] = __float2bfloat16(vv[j] - __bfloat162float(hh[j]));
    }
    __nv_bfloat162* hp = (__nv_bfloat162*)h + 2 * (size_t)i;
    __nv_bfloat162* lp = (__nv_bfloat162*)l + 2 * (size_t)i;
    hp[0] = __halves2bfloat162(hh[0], hh[1]);
    hp[1] = __halves2bfloat162(hh[2], hh[3]);
    lp[0] = __halves2bfloat162(ll[0], ll[1]);
    lp[1] = __halves2bfloat162(ll[2], ll[3]);
}

// ---------------------------------------------------------------------------
// mma.sync bf16x3 GEMM (hh + hl + lh), direct accumulation (smooth paths).
// Unchanged from R10 (measured-passing).
// ---------------------------------------------------------------------------
#define GB_BM 128
#define GB_BN 128
#define GB_BK 32
#define LDP 40
#define TILE_ELEMS (128 * LDP)            // 5120 halves
#define STG_BYTES (4 * TILE_ELEMS * 2)    // Ah, Al, Bh, Bl per stage
#define GEMM_SMEM (2 * STG_BYTES)         // 81920 B
#define NCHUNK (DMODEL / GB_BK)           // 64

__global__ __launch_bounds__(256, 2) void gemm_bf16x3(
    const __nv_bfloat16* __restrict__ Ah, const __nv_bfloat16* __restrict__ Al,
    const __nv_bfloat16* __restrict__ Bh, const __nv_bfloat16* __restrict__ Bl,
    const float* __restrict__ bias, float* __restrict__ C)
{
    extern __shared__ __nv_bfloat16 smem[];
    const uint32_t sbase = smem_u32(smem);

    const int tid  = threadIdx.x;
    const int wid  = tid >> 5;
    const int lane = tid & 31;
    const int wm   = wid & 1;
    const int wn   = wid >> 1;
    const int bm   = blockIdx.y * GB_BM;
    const int bn   = blockIdx.x * GB_BN;

    float sum[4][4][4];
#pragma unroll
    for (int m = 0; m < 4; m++)
#pragma unroll
        for (int n = 0; n < 4; n++)
#pragma unroll
            for (int e = 0; e < 4; e++) sum[m][n][e] = 0.f;

    const int li0 = tid * 2;

    auto prefetch = [&](int chunk) {
        const uint32_t st = sbase + (uint32_t)(chunk & 1) * STG_BYTES;
        const int kk = chunk * GB_BK;
#pragma unroll
        for (int i = 0; i < 2; i++) {
            int idx = li0 + i;
            int r = idx >> 2;
            int c = (idx & 3) * 8;
            uint32_t soff = (uint32_t)(r * LDP + c) * 2;
            size_t ga = (size_t)(bm + r) * DMODEL + kk + c;
            size_t gb = (size_t)(bn + r) * DMODEL + kk + c;
            CP_ASYNC16(st + soff, Ah + ga);
            CP_ASYNC16(st + (uint32_t)TILE_ELEMS * 2 + soff, Al + ga);
            CP_ASYNC16(st + (uint32_t)(2 * TILE_ELEMS) * 2 + soff, Bh + gb);
            CP_ASYNC16(st + (uint32_t)(3 * TILE_ELEMS) * 2 + soff, Bl + gb);
        }
    };

    prefetch(0);
    CP_ASYNC_COMMIT();

    const int a_row = wm * 64 + (lane & 15);
    const int a_colh = (lane >> 4) * 8;
    const int bp_row = wn * 32 + ((lane >> 4) & 1) * 8 + (lane & 7);
    const int bp_colh = ((lane >> 3) & 1) * 8;

    for (int chunk = 0; chunk < NCHUNK; chunk++) {
        if (chunk + 1 < NCHUNK) {
            prefetch(chunk + 1);
            CP_ASYNC_COMMIT();
            CP_ASYNC_WAIT1();
        } else {
            CP_ASYNC_WAIT0();
        }
        __syncthreads();

        const uint32_t st = sbase + (uint32_t)(chunk & 1) * STG_BYTES;

#pragma unroll
        for (int ks = 0; ks < GB_BK; ks += 16) {
            uint32_t ah[4][4], al[4][4], bh[4][2], bl[4][2];
#pragma unroll
            for (int m = 0; m < 4; m++) {
                uint32_t off = (uint32_t)((a_row + m * 16) * LDP + ks + a_colh) * 2;
                ldsm_x4(ah[m], st + off);
                ldsm_x4(al[m], st + (uint32_t)TILE_ELEMS * 2 + off);
            }
#pragma unroll
            for (int np = 0; np < 2; np++) {
                uint32_t off = (uint32_t)((bp_row + np * 16) * LDP + ks + bp_colh) * 2;
                uint32_t rh[4], rl[4];
                ldsm_x4(rh, st + (uint32_t)(2 * TILE_ELEMS) * 2 + off);
                ldsm_x4(rl, st + (uint32_t)(3 * TILE_ELEMS) * 2 + off);
                bh[2 * np + 0][0] = rh[0]; bh[2 * np + 0][1] = rh[1];
                bh[2 * np + 1][0] = rh[2]; bh[2 * np + 1][1] = rh[3];
                bl[2 * np + 0][0] = rl[0]; bl[2 * np + 0][1] = rl[1];
                bl[2 * np + 1][0] = rl[2]; bl[2 * np + 1][1] = rl[3];
            }
#pragma unroll
            for (int m = 0; m < 4; m++)
#pragma unroll
                for (int n = 0; n < 4; n++) {
                    mma_bf16(sum[m][n], ah[m], bh[n][0], bh[n][1]);
                    mma_bf16(sum[m][n], ah[m], bl[n][0], bl[n][1]);
                    mma_bf16(sum[m][n], al[m], bh[n][0], bh[n][1]);
                }
        }
        __syncthreads();
    }

#pragma unroll
    for (int m = 0; m < 4; m++) {
        int row0 = bm + wm * 64 + m * 16 + (lane >> 2);
#pragma unroll
        for (int n = 0; n < 4; n++) {
            int col = bn + wn * 32 + n * 8 + (lane & 3) * 2;
            float2 bb = __ldg((const float2*)&bias[col]);
            float2 w0 = {sum[m][n][0] + bb.x, sum[m][n][1] + bb.y};
            float2 w1 = {sum[m][n][2] + bb.x, sum[m][n][3] + bb.y};
            *(float2*)(C + (size_t)row0 * DMODEL + col) = w0;
            *(float2*)(C + (size_t)(row0 + 8) * DMODEL + col) = w1;
        }
    }
}

// ---------------------------------------------------------------------------
// Fused causal attention v2b: 64-row Q blocks, Ps aliased onto Ks.
// FIX vs v2: all smem row strides padded to multiples of 4 floats
// (QS_LD=KS_LD=PS_LD=68) so every float4 access is 16B-aligned.
// 100 KB smem -> 2 CTAs/SM. Per-output arithmetic order BIT-IDENTICAL
// to the measured-passing version.
// ---------------------------------------------------------------------------
#define QS_LD 68
#define KS_LD 68
#define PS_LD 68            // 64*68 = 4352 floats <= Ks region (128*68 = 8704)
#define ATTN_SMEM_FLOATS (128 * QS_LD + 128 * KS_LD + 64 * 128)   // 25600

__global__ __launch_bounds__(256, 2) void attn_kernel()
{
    extern __shared__ float sm[];
    float* Qs = sm;                       // [d][i]  128 x 68 (i = 0..63)
    float* Ks = Qs + 128 * QS_LD;         // [d][j]  128 x 68
    float* Ps = Ks;                       // [j][il] 64 x 68 (aliases Ks)
    float* Vs = Ks + 128 * KS_LD;         // [j][d]  64 x 128

    const int tid = threadIdx.x;
    const int tr  = tid >> 4;    // 0..15 (q-row group: rows tr*4..tr*4+3)
    const int tc  = tid & 15;    // 0..15 (k-col group: cols tc*4..tc*4+3)
    const int qb  = blockIdx.x;  // q block 0..31 (64 rows each)
    const int bh  = blockIdx.y;  // 0..31

    const size_t base = (size_t)bh * (S_LEN * DKH);
    const float* qp = g_q + base + (size_t)qb * 64 * DKH;
    const float* kp0 = g_k + base;
    const float* vp0 = g_v + base;

    // Load Q block transposed: Qs[d][i], 64 rows x 128 d
#pragma unroll
    for (int it = 0; it < 8; it++) {
        int slot = tid + (it << 8);          // 0..2047
        int i  = slot >> 5;                  // 0..63
        int d0 = (slot & 31) << 2;
        float4 v = *(const float4*)(qp + (size_t)i * DKH + d0);
        Qs[(d0 + 0) * QS_LD + i] = v.x;
        Qs[(d0 + 1) * QS_LD + i] = v.y;
        Qs[(d0 + 2) * QS_LD + i] = v.z;
        Qs[(d0 + 3) * QS_LD + i] = v.w;
    }

    float m_[4], l_[4], o_[4][8];
#pragma unroll
    for (int r = 0; r < 4; r++) {
        m_[r] = -INFINITY;
        l_[r] = 0.f;
#pragma unroll
        for (int c = 0; c < 8; c++) o_[r][c] = 0.f;
    }

    const int nkb = qb + 1;                  // 64-key tiles (causal)
    for (int kb = 0; kb < nkb; kb++) {
        __syncthreads();   // prev PV done with Ps(=Ks)/Vs; Q ready on kb=0

        const float* kp = kp0 + (size_t)kb * 64 * DKH;
        const float* vp = vp0 + (size_t)kb * 64 * DKH;
#pragma unroll
        for (int it = 0; it < 8; it++) {
            int slot = tid + (it << 8);
            int j  = slot >> 5;
            int d0 = (slot & 31) << 2;
            float4 v = *(const float4*)(kp + (size_t)j * DKH + d0);
            Ks[(d0 + 0) * KS_LD + j] = v.x;
            Ks[(d0 + 1) * KS_LD + j] = v.y;
            Ks[(d0 + 2) * KS_LD + j] = v.z;
            Ks[(d0 + 3) * KS_LD + j] = v.w;
            float4 w = *(const float4*)(vp + (size_t)j * DKH + d0);
            *(float4*)&Vs[j * 128 + d0] = w;
        }
        __syncthreads();

        // S = Q K^T  (4 rows x 4 cols per thread)
        float sacc[4][4];
#pragma unroll
        for (int r = 0; r < 4; r++)
#pragma unroll
            for (int c = 0; c < 4; c++) sacc[r][c] = 0.f;

#pragma unroll 4
        for (int d = 0; d < 128; d++) {
            float4 x = *(const float4*)(Qs + d * QS_LD + (tr << 2));
            float4 y = *(const float4*)(Ks + d * KS_LD + (tc << 2));
            float av[4] = {x.x, x.y, x.z, x.w};
            float bv[4] = {y.x, y.y, y.z, y.w};
#pragma unroll
            for (int r = 0; r < 4; r++)
#pragma unroll
                for (int c = 0; c < 4; c++) sacc[r][c] += av[r] * bv[c];
        }
        __syncthreads();   // all warps done reading Ks before Ps overwrites it

        // floor + causal mask + online softmax; write P into Ps (alias of Ks)
        const int gj0 = kb * 64 + (tc << 2);
#pragma unroll
        for (int r = 0; r < 4; r++) {
            int il = (tr << 2) + r;
            int gi = qb * 64 + il;
            float mrow = -INFINITY;
#pragma unroll
            for (int c = 0; c < 4; c++) {
                float s_ = floorf(sacc[r][c] / SQRT_DM);
                if (gj0 + c > gi) s_ = -INFINITY;
                sacc[r][c] = s_;
                mrow = fmaxf(mrow, s_);
            }
#pragma unroll
            for (int off = 8; off >= 1; off >>= 1)
                mrow = fmaxf(mrow, __shfl_xor_sync(0xffffffffu, mrow, off));

            float mnew = fmaxf(m_[r], mrow);
            float f = __expf(m_[r] - mnew);
            m_[r] = mnew;

            float rs = 0.f;
#pragma unroll
            for (int c = 0; c < 4; c++) {
                float p = __expf(sacc[r][c] - mnew);   // 0 for masked (-inf)
                rs += p;
                Ps[((tc << 2) + c) * PS_LD + il] = p;
            }
#pragma unroll
            for (int off = 8; off >= 1; off >>= 1)
                rs += __shfl_xor_sync(0xffffffffu, rs, off);

            l_[r] = l_[r] * f + rs;
#pragma unroll
            for (int c = 0; c < 8; c++) o_[r][c] *= f;
        }
        __syncthreads();   // Ps fully written, Vs ready

        // O += P V  (4 rows x 8 dims per thread)
#pragma unroll 2
        for (int j = 0; j < 64; j++) {
            float4 x = *(const float4*)(Ps + j * PS_LD + (tr << 2));
            const float* vr = Vs + j * 128 + (tc << 2);
            float av[4] = {x.x, x.y, x.z, x.w};
            float bv[8] = {vr[0], vr[1], vr[2], vr[3],
                           vr[64], vr[65], vr[66], vr[67]};
#pragma unroll
            for (int r = 0; r < 4; r++)
#pragma unroll
                for (int c = 0; c < 8; c++) o_[r][c] += av[r] * bv[c];
        }
    }

    // normalize + write
    float* op = g_o + base + (size_t)qb * 64 * DKH;
#pragma unroll
    for (int r = 0; r < 4; r++) {
        int il = (tr << 2) + r;
        float inv = 1.0f / l_[r];
#pragma unroll
        for (int jh = 0; jh < 2; jh++) {
            int col = (jh ? (64 + (tc << 2)) : (tc << 2));
            float4 w;
            w.x = o_[r][jh * 4 + 0] * inv;
            w.y = o_[r][jh * 4 + 1] * inv;
            w.z = o_[r][jh * 4 + 2] * inv;
            w.w = o_[r][jh * 4 + 3] * inv;
            *(float4*)(op + (size_t)il * DKH + col) = w;
        }
    }
}

// ---------------------------------------------------------------------------
extern "C" void kernel_launch(void* const* d_in, const int* in_sizes, int n_in,
                              void* d_out, int out_size)
{
    const float* key   = (const float*)d_in[0];
    const float* query = (const float*)d_in[1];
    const float* value = (const float*)d_in[2];
    const float* Wq = (const float*)d_in[4];
    const float* bq = (const float*)d_in[5];
    const float* Wk = (const float*)d_in[6];
    const float* bk = (const float*)d_in[7];
    const float* Wv = (const float*)d_in[8];
    const float* bv = (const float*)d_in[9];
    const float* Wo = (const float*)d_in[10];
    const float* bo = (const float*)d_in[11];
    float* out = (float*)d_out;

    float *gq, *gk, *gv, *go;
    __nv_bfloat16 *xh, *xl, *wh, *wl;
    cudaGetSymbolAddress((void**)&gq, g_q);
    cudaGetSymbolAddress((void**)&gk, g_k);
    cudaGetSymbolAddress((void**)&gv, g_v);
    cudaGetSymbolAddress((void**)&go, g_o);
    cudaGetSymbolAddress((void**)&xh, g_xh);
    cudaGetSymbolAddress((void**)&xl, g_xl);
    cudaGetSymbolAddress((void**)&wh, g_wh);
    cudaGetSymbolAddress((void**)&wl, g_wl);

    cudaFuncSetAttribute(gemm_bf16x3,
                         cudaFuncAttributeMaxDynamicSharedMemorySize, GEMM_SMEM);
    const int attn_smem = ATTN_SMEM_FLOATS * (int)sizeof(float);   // 102400 B
    cudaFuncSetAttribute(attn_kernel,
                         cudaFuncAttributeMaxDynamicSharedMemorySize, attn_smem);

    const int nx4 = MROWS * DMODEL / 4;
    const int nw4 = DMODEL * DMODEL / 4;
    dim3 gfp32(DMODEL / 128, MROWS / 128);       // (16, 32)
    dim3 gmma(DMODEL / GB_BN, MROWS / GB_BM);    // (16, 32)

    // Q/K projections: floor-critical -> fp32 SIMT (R1-identical numerics)
    gemm_nt_bias<<<gfp32, 256>>>(query, Wq, bq, gq);
    gemm_nt_bias<<<gfp32, 256>>>(key,   Wk, bk, gk);

    // V projection: smooth -> bf16x3 mma (direct accumulation)
    split2_bf16<<<nx4 / 256, 256>>>(value, xh, xl, nx4);
    split2_bf16<<<nw4 / 256, 256>>>(Wv, wh, wl, nw4);
    gemm_bf16x3<<<gmma, 256, GEMM_SMEM>>>(xh, xl, wh, wl, bv, gv);

    // Attention (fp32, 64-row blocks, 2 CTAs/SM)
    attn_kernel<<<dim3(S_LEN / 64, BATCH * NHEADS), 256, attn_smem>>>();

    // Output projection: smooth -> bf16x3 mma (direct accumulation)
    split2_bf16<<<nx4 / 256, 256>>>(go, xh, xl, nx4);
    split2_bf16<<<nw4 / 256, 256>>>(Wo, wh, wl, nw4);
    gemm_bf16x3<<<gmma, 256, GEMM_SMEM>>>(xh, xl, wh, wl, bo, out);
}

// round 13
// speedup vs baseline: 1.0315x; 1.0315x over previous
#include <cuda_runtime.h>
#include <cuda_bf16.h>
#include <math.h>
#include <stdint.h>

// Problem constants
#define S_LEN 2048
#define DMODEL 2048
#define NHEADS 16
#define DKH 128
#define BATCH 2
#define MROWS (BATCH * S_LEN)   // 4096
#define SQRT_DM 45.254833995939045f

// ---------------------------------------------------------------------------
// Scratch (__device__ globals; no allocation allowed)
// ---------------------------------------------------------------------------
__device__ float g_q[(size_t)MROWS * DMODEL];
__device__ float g_k[(size_t)MROWS * DMODEL];
__device__ float g_v[(size_t)MROWS * DMODEL];
__device__ float g_o[(size_t)MROWS * DMODEL];
__device__ __nv_bfloat16 g_xh[(size_t)MROWS * DMODEL];
__device__ __nv_bfloat16 g_xl[(size_t)MROWS * DMODEL];
__device__ __nv_bfloat16 g_wh[(size_t)DMODEL * DMODEL];
__device__ __nv_bfloat16 g_wl[(size_t)DMODEL * DMODEL];

// ---------------------------------------------------------------------------
// PTX helpers (base sm_100 target safe: mma.sync / ldmatrix / cp.async only)
// ---------------------------------------------------------------------------
static __device__ __forceinline__ uint32_t smem_u32(const void* p) {
    uint32_t a;
    asm("{ .reg .u64 t; cvta.to.shared.u64 t, %1; cvt.u32.u64 %0, t; }"
        : "=r"(a) : "l"(p));
    return a;
}

#define CP_ASYNC16(saddr, gaddr) \
    asm volatile("cp.async.cg.shared.global [%0], [%1], 16;" :: "r"(saddr), "l"(gaddr))
#define CP_ASYNC_COMMIT() asm volatile("cp.async.commit_group;" ::: "memory")
#define CP_ASYNC_WAIT0()  asm volatile("cp.async.wait_group 0;" ::: "memory")
#define CP_ASYNC_WAIT1()  asm volatile("cp.async.wait_group 1;" ::: "memory")

static __device__ __forceinline__ void ldsm_x4(uint32_t (&r)[4], uint32_t addr) {
    asm volatile("ldmatrix.sync.aligned.m8n8.x4.shared.b16 {%0,%1,%2,%3}, [%4];"
                 : "=r"(r[0]), "=r"(r[1]), "=r"(r[2]), "=r"(r[3]) : "r"(addr));
}
static __device__ __forceinline__ void mma_bf16(float (&d)[4],
                                                const uint32_t (&a)[4],
                                                const uint32_t b0, const uint32_t b1) {
    asm volatile("mma.sync.aligned.m16n8k16.row.col.f32.bf16.bf16.f32 "
                 "{%0,%1,%2,%3}, {%4,%5,%6,%7}, {%8,%9}, {%0,%1,%2,%3};"
                 : "+f"(d[0]), "+f"(d[1]), "+f"(d[2]), "+f"(d[3])
                 : "r"(a[0]), "r"(a[1]), "r"(a[2]), "r"(a[3]),
                   "r"(b0), "r"(b1));
}

// ---------------------------------------------------------------------------
// fp32 SIMT GEMM (R1, measured-passing): C = A @ W^T + bias
// Used for the floor-critical Q/K projections. UNCHANGED numerics.
// ---------------------------------------------------------------------------
__global__ __launch_bounds__(256) void gemm_nt_bias(
    const float* __restrict__ A, const float* __restrict__ W,
    const float* __restrict__ bias, float* __restrict__ C)
{
    const int K = DMODEL;
    const int N = DMODEL;

    __shared__ float As[16][132];
    __shared__ float Bs[16][132];

    const int tid = threadIdx.x;
    const int tr  = tid >> 4;
    const int tc  = tid & 15;
    const int bm  = blockIdx.y << 7;
    const int bn  = blockIdx.x << 7;

    const int lr = tid >> 2;
    const int lk = (tid & 3) << 2;

    const float* Ar0 = A + (size_t)(bm + lr) * K + lk;
    const float* Ar1 = A + (size_t)(bm + 64 + lr) * K + lk;
    const float* Wr0 = W + (size_t)(bn + lr) * K + lk;
    const float* Wr1 = W + (size_t)(bn + 64 + lr) * K + lk;

    float acc[8][8];
#pragma unroll
    for (int i = 0; i < 8; i++)
#pragma unroll
        for (int j = 0; j < 8; j++) acc[i][j] = 0.f;

    float4 pa0 = *(const float4*)(Ar0);
    float4 pa1 = *(const float4*)(Ar1);
    float4 pb0 = *(const float4*)(Wr0);
    float4 pb1 = *(const float4*)(Wr1);

    for (int kt = 0; kt < K; kt += 16) {
        As[lk + 0][lr] = pa0.x; As[lk + 1][lr] = pa0.y;
        As[lk + 2][lr] = pa0.z; As[lk + 3][lr] = pa0.w;
        As[lk + 0][64 + lr] = pa1.x; As[lk + 1][64 + lr] = pa1.y;
        As[lk + 2][64 + lr] = pa1.z; As[lk + 3][64 + lr] = pa1.w;
        Bs[lk + 0][lr] = pb0.x; Bs[lk + 1][lr] = pb0.y;
        Bs[lk + 2][lr] = pb0.z; Bs[lk + 3][lr] = pb0.w;
        Bs[lk + 0][64 + lr] = pb1.x; Bs[lk + 1][64 + lr] = pb1.y;
        Bs[lk + 2][64 + lr] = pb1.z; Bs[lk + 3][64 + lr] = pb1.w;
        __syncthreads();

        if (kt + 16 < K) {
            pa0 = *(const float4*)(Ar0 + kt + 16);
            pa1 = *(const float4*)(Ar1 + kt + 16);
            pb0 = *(const float4*)(Wr0 + kt + 16);
            pb1 = *(const float4*)(Wr1 + kt + 16);
        }

#pragma unroll
        for (int k = 0; k < 16; k++) {
            float4 x0 = *(const float4*)&As[k][tr << 2];
            float4 x1 = *(const float4*)&As[k][64 + (tr << 2)];
            float4 y0 = *(const float4*)&Bs[k][tc << 2];
            float4 y1 = *(const float4*)&Bs[k][64 + (tc << 2)];
            float av[8] = {x0.x, x0.y, x0.z, x0.w, x1.x, x1.y, x1.z, x1.w};
            float bv[8] = {y0.x, y0.y, y0.z, y0.w, y1.x, y1.y, y1.z, y1.w};
#pragma unroll
            for (int i = 0; i < 8; i++)
#pragma unroll
                for (int j = 0; j < 8; j++) acc[i][j] += av[i] * bv[j];
        }
        __syncthreads();
    }

#pragma unroll
    for (int i = 0; i < 8; i++) {
        int row = bm + ((i < 4) ? ((tr << 2) + i) : (64 + (tr << 2) + i - 4));
#pragma unroll
        for (int jh = 0; jh < 2; jh++) {
            int col = bn + (jh ? (64 + (tc << 2)) : (tc << 2));
            float4 r;
            r.x = acc[i][jh * 4 + 0] + __ldg(&bias[col + 0]);
            r.y = acc[i][jh * 4 + 1] + __ldg(&bias[col + 1]);
            r.z = acc[i][jh * 4 + 2] + __ldg(&bias[col + 2]);
            r.w = acc[i][jh * 4 + 3] + __ldg(&bias[col + 3]);
            *(float4*)(C + (size_t)row * N + col) = r;
        }
    }
}

// ---------------------------------------------------------------------------
// Split fp32 -> (bf16 hi, bf16 lo); residual exact in fp32.
// ---------------------------------------------------------------------------
__global__ __launch_bounds__(256) void split2_bf16(
    const float* __restrict__ x,
    __nv_bfloat16* __restrict__ h, __nv_bfloat16* __restrict__ l, int n4)
{
    int i = blockIdx.x * blockDim.x + threadIdx.x;
    if (i >= n4) return;
    float4 v = ((const float4*)x)[i];
    float vv[4] = {v.x, v.y, v.z, v.w};
    __nv_bfloat16 hh[4], ll[4];
#pragma unroll
    for (int j = 0; j < 4; j++) {
        hh[j] = __float2bfloat16(vv[j]);
        ll[j] = __float2bfloat16(vv[j] - __bfloat162float(hh[j]));
    }
    __nv_bfloat162* hp = (__nv_bfloat162*)h + 2 * (size_t)i;
    __nv_bfloat162* lp = (__nv_bfloat162*)l + 2 * (size_t)i;
    hp[0] = __halves2bfloat162(hh[0], hh[1]);
    hp[1] = __halves2bfloat162(hh[2], hh[3]);
    lp[0] = __halves2bfloat162(ll[0], ll[1]);
    lp[1] = __halves2bfloat162(ll[2], ll[3]);
}

// ---------------------------------------------------------------------------
// mma.sync bf16x3 GEMM (hh + hl + lh), direct accumulation (smooth paths).
// Unchanged from R10 (measured-passing).
// ---------------------------------------------------------------------------
#define GB_BM 128
#define GB_BN 128
#define GB_BK 32
#define LDP 40
#define TILE_ELEMS (128 * LDP)            // 5120 halves
#define STG_BYTES (4 * TILE_ELEMS * 2)    // Ah, Al, Bh, Bl per stage
#define GEMM_SMEM (2 * STG_BYTES)         // 81920 B
#define NCHUNK (DMODEL / GB_BK)           // 64

__global__ __launch_bounds__(256, 2) void gemm_bf16x3(
    const __nv_bfloat16* __restrict__ Ah, const __nv_bfloat16* __restrict__ Al,
    const __nv_bfloat16* __restrict__ Bh, const __nv_bfloat16* __restrict__ Bl,
    const float* __restrict__ bias, float* __restrict__ C)
{
    extern __shared__ __nv_bfloat16 smem[];
    const uint32_t sbase = smem_u32(smem);

    const int tid  = threadIdx.x;
    const int wid  = tid >> 5;
    const int lane = tid & 31;
    const int wm   = wid & 1;
    const int wn   = wid >> 1;
    const int bm   = blockIdx.y * GB_BM;
    const int bn   = blockIdx.x * GB_BN;

    float sum[4][4][4];
#pragma unroll
    for (int m = 0; m < 4; m++)
#pragma unroll
        for (int n = 0; n < 4; n++)
#pragma unroll
            for (int e = 0; e < 4; e++) sum[m][n][e] = 0.f;

    const int li0 = tid * 2;

    auto prefetch = [&](int chunk) {
        const uint32_t st = sbase + (uint32_t)(chunk & 1) * STG_BYTES;
        const int kk = chunk * GB_BK;
#pragma unroll
        for (int i = 0; i < 2; i++) {
            int idx = li0 + i;
            int r = idx >> 2;
            int c = (idx & 3) * 8;
            uint32_t soff = (uint32_t)(r * LDP + c) * 2;
            size_t ga = (size_t)(bm + r) * DMODEL + kk + c;
            size_t gb = (size_t)(bn + r) * DMODEL + kk + c;
            CP_ASYNC16(st + soff, Ah + ga);
            CP_ASYNC16(st + (uint32_t)TILE_ELEMS * 2 + soff, Al + ga);
            CP_ASYNC16(st + (uint32_t)(2 * TILE_ELEMS) * 2 + soff, Bh + gb);
            CP_ASYNC16(st + (uint32_t)(3 * TILE_ELEMS) * 2 + soff, Bl + gb);
        }
    };

    prefetch(0);
    CP_ASYNC_COMMIT();

    const int a_row = wm * 64 + (lane & 15);
    const int a_colh = (lane >> 4) * 8;
    const int bp_row = wn * 32 + ((lane >> 4) & 1) * 8 + (lane & 7);
    const int bp_colh = ((lane >> 3) & 1) * 8;

    for (int chunk = 0; chunk < NCHUNK; chunk++) {
        if (chunk + 1 < NCHUNK) {
            prefetch(chunk + 1);
            CP_ASYNC_COMMIT();
            CP_ASYNC_WAIT1();
        } else {
            CP_ASYNC_WAIT0();
        }
        __syncthreads();

        const uint32_t st = sbase + (uint32_t)(chunk & 1) * STG_BYTES;

#pragma unroll
        for (int ks = 0; ks < GB_BK; ks += 16) {
            uint32_t ah[4][4], al[4][4], bh[4][2], bl[4][2];
#pragma unroll
            for (int m = 0; m < 4; m++) {
                uint32_t off = (uint32_t)((a_row + m * 16) * LDP + ks + a_colh) * 2;
                ldsm_x4(ah[m], st + off);
                ldsm_x4(al[m], st + (uint32_t)TILE_ELEMS * 2 + off);
            }
#pragma unroll
            for (int np = 0; np < 2; np++) {
                uint32_t off = (uint32_t)((bp_row + np * 16) * LDP + ks + bp_colh) * 2;
                uint32_t rh[4], rl[4];
                ldsm_x4(rh, st + (uint32_t)(2 * TILE_ELEMS) * 2 + off);
                ldsm_x4(rl, st + (uint32_t)(3 * TILE_ELEMS) * 2 + off);
                bh[2 * np + 0][0] = rh[0]; bh[2 * np + 0][1] = rh[1];
                bh[2 * np + 1][0] = rh[2]; bh[2 * np + 1][1] = rh[3];
                bl[2 * np + 0][0] = rl[0]; bl[2 * np + 0][1] = rl[1];
                bl[2 * np + 1][0] = rl[2]; bl[2 * np + 1][1] = rl[3];
            }
#pragma unroll
            for (int m = 0; m < 4; m++)
#pragma unroll
                for (int n = 0; n < 4; n++) {
                    mma_bf16(sum[m][n], ah[m], bh[n][0], bh[n][1]);
                    mma_bf16(sum[m][n], ah[m], bl[n][0], bl[n][1]);
                    mma_bf16(sum[m][n], al[m], bh[n][0], bh[n][1]);
                }
        }
        __syncthreads();
    }

#pragma unroll
    for (int m = 0; m < 4; m++) {
        int row0 = bm + wm * 64 + m * 16 + (lane >> 2);
#pragma unroll
        for (int n = 0; n < 4; n++) {
            int col = bn + wn * 32 + n * 8 + (lane & 3) * 2;
            float2 bb = __ldg((const float2*)&bias[col]);
            float2 w0 = {sum[m][n][0] + bb.x, sum[m][n][1] + bb.y};
            float2 w1 = {sum[m][n][2] + bb.x, sum[m][n][3] + bb.y};
            *(float2*)(C + (size_t)row0 * DMODEL + col) = w0;
            *(float2*)(C + (size_t)(row0 + 8) * DMODEL + col) = w1;
        }
    }
}

// ---------------------------------------------------------------------------
// Fused causal attention v3: 128-row Q block x 128-key tiles, Ps aliased
// onto dead Ks. 8x8 per-thread tiles in BOTH S and PV -> 1.0 B smem/FMA
// (vs 1.5 in the 64-key version). Scores are the same ascending-d FMA
// chains -> BIT-IDENTICAL floor-flip set; only smooth softmax-merge
// rounding differs. 200.7 KB smem, 1 CTA/SM.
// ---------------------------------------------------------------------------
#define QS_LD 132
#define KS_LD 132
#define PS_LD 132
#define ATTN_SMEM_FLOATS (128 * QS_LD + 128 * KS_LD + 128 * 128)  // 50176

__global__ __launch_bounds__(256) void attn_kernel()
{
    extern __shared__ float sm[];
    float* Qs = sm;                       // [d][i]  128 x 132
    float* Ks = Qs + 128 * QS_LD;         // [d][j]  128 x 132
    float* Ps = Ks;                       // [j][i]  128 x 132 (aliases Ks)
    float* Vs = Ks + 128 * KS_LD;         // [j][d]  128 x 128

    const int tid = threadIdx.x;
    const int tr  = tid >> 4;    // 0..15
    const int tc  = tid & 15;    // 0..15
    const int qb  = gridDim.x - 1 - blockIdx.x;  // heavy blocks first
    const int bh  = blockIdx.y;  // 0..31

    const size_t base = (size_t)bh * (S_LEN * DKH);
    const float* qp = g_q + base + (size_t)qb * 128 * DKH;
    const float* kp0 = g_k + base;
    const float* vp0 = g_v + base;

    // Load Q block transposed: Qs[d][i]
#pragma unroll
    for (int it = 0; it < 16; it++) {
        int slot = tid + (it << 8);          // 0..4095
        int i  = slot >> 5;                  // 0..127
        int d0 = (slot & 31) << 2;
        float4 v = *(const float4*)(qp + (size_t)i * DKH + d0);
        Qs[(d0 + 0) * QS_LD + i] = v.x;
        Qs[(d0 + 1) * QS_LD + i] = v.y;
        Qs[(d0 + 2) * QS_LD + i] = v.z;
        Qs[(d0 + 3) * QS_LD + i] = v.w;
    }

    float m_[8], l_[8], o_[8][8];
#pragma unroll
    for (int r = 0; r < 8; r++) {
        m_[r] = -INFINITY;
        l_[r] = 0.f;
#pragma unroll
        for (int c = 0; c < 8; c++) o_[r][c] = 0.f;
    }

    const int nkb = qb + 1;                  // 128-key tiles (causal)
    for (int kb = 0; kb < nkb; kb++) {
        __syncthreads();   // prev PV done with Ps(=Ks)/Vs; Q ready on kb=0

        const float* kp = kp0 + (size_t)kb * 128 * DKH;
        const float* vp = vp0 + (size_t)kb * 128 * DKH;
#pragma unroll
        for (int it = 0; it < 16; it++) {
            int slot = tid + (it << 8);
            int j  = slot >> 5;              // 0..127
            int d0 = (slot & 31) << 2;
            float4 v = *(const float4*)(kp + (size_t)j * DKH + d0);
            Ks[(d0 + 0) * KS_LD + j] = v.x;
            Ks[(d0 + 1) * KS_LD + j] = v.y;
            Ks[(d0 + 2) * KS_LD + j] = v.z;
            Ks[(d0 + 3) * KS_LD + j] = v.w;
            float4 w = *(const float4*)(vp + (size_t)j * DKH + d0);
            *(float4*)&Vs[j * 128 + d0] = w;
        }
        __syncthreads();

        // S = Q K^T  (8 rows x 8 cols per thread)
        float sacc[8][8];
#pragma unroll
        for (int r = 0; r < 8; r++)
#pragma unroll
            for (int c = 0; c < 8; c++) sacc[r][c] = 0.f;

#pragma unroll 4
        for (int d = 0; d < 128; d++) {
            float4 x0 = *(const float4*)(Qs + d * QS_LD + (tr << 2));
            float4 x1 = *(const float4*)(Qs + d * QS_LD + 64 + (tr << 2));
            float4 y0 = *(const float4*)(Ks + d * KS_LD + (tc << 2));
            float4 y1 = *(const float4*)(Ks + d * KS_LD + 64 + (tc << 2));
            float av[8] = {x0.x, x0.y, x0.z, x0.w, x1.x, x1.y, x1.z, x1.w};
            float bv[8] = {y0.x, y0.y, y0.z, y0.w, y1.x, y1.y, y1.z, y1.w};
#pragma unroll
            for (int r = 0; r < 8; r++)
#pragma unroll
                for (int c = 0; c < 8; c++) sacc[r][c] += av[r] * bv[c];
        }
        __syncthreads();   // all warps done reading Ks before Ps overwrites it

        // floor + causal mask + online softmax; write P into Ps (alias of Ks)
#pragma unroll
        for (int r = 0; r < 8; r++) {
            int il = (r < 4) ? ((tr << 2) + r) : (64 + (tr << 2) + r - 4);
            int gi = qb * 128 + il;
            float mrow = -INFINITY;
#pragma unroll
            for (int cg = 0; cg < 2; cg++)
#pragma unroll
                for (int c = 0; c < 4; c++) {
                    int jloc = cg * 64 + (tc << 2) + c;
                    float s_ = floorf(sacc[r][cg * 4 + c] / SQRT_DM);
                    if (kb * 128 + jloc > gi) s_ = -INFINITY;
                    sacc[r][cg * 4 + c] = s_;
                    mrow = fmaxf(mrow, s_);
                }
#pragma unroll
            for (int off = 8; off >= 1; off >>= 1)
                mrow = fmaxf(mrow, __shfl_xor_sync(0xffffffffu, mrow, off));

            float mnew = fmaxf(m_[r], mrow);
            float f = __expf(m_[r] - mnew);
            m_[r] = mnew;

            float rs = 0.f;
#pragma unroll
            for (int cg = 0; cg < 2; cg++)
#pragma unroll
                for (int c = 0; c < 4; c++) {
                    int jloc = cg * 64 + (tc << 2) + c;
                    float p = __expf(sacc[r][cg * 4 + c] - mnew);  // 0 if masked
                    rs += p;
                    Ps[jloc * PS_LD + il] = p;
                }
#pragma unroll
            for (int off = 8; off >= 1; off >>= 1)
                rs += __shfl_xor_sync(0xffffffffu, rs, off);

            l_[r] = l_[r] * f + rs;
#pragma unroll
            for (int c = 0; c < 8; c++) o_[r][c] *= f;
        }
        __syncthreads();   // Ps fully written, Vs ready

        // O += P V  (8 rows x 8 dims per thread)
#pragma unroll 2
        for (int j = 0; j < 128; j++) {
            float4 x0 = *(const float4*)(Ps + j * PS_LD + (tr << 2));
            float4 x1 = *(const float4*)(Ps + j * PS_LD + 64 + (tr << 2));
            float4 y0 = *(const float4*)(Vs + j * 128 + (tc << 2));
            float4 y1 = *(const float4*)(Vs + j * 128 + 64 + (tc << 2));
            float av[8] = {x0.x, x0.y, x0.z, x0.w, x1.x, x1.y, x1.z, x1.w};
            float bv[8] = {y0.x, y0.y, y0.z, y0.w, y1.x, y1.y, y1.z, y1.w};
#pragma unroll
            for (int r = 0; r < 8; r++)
#pragma unroll
                for (int c = 0; c < 8; c++) o_[r][c] += av[r] * bv[c];
        }
    }

    // normalize + write
    float* op = g_o + base + (size_t)qb * 128 * DKH;
#pragma unroll
    for (int r = 0; r < 8; r++) {
        int il = (r < 4) ? ((tr << 2) + r) : (64 + (tr << 2) + r - 4);
        float inv = 1.0f / l_[r];
#pragma unroll
        for (int jh = 0; jh < 2; jh++) {
            int col = (jh ? (64 + (tc << 2)) : (tc << 2));
            float4 w;
            w.x = o_[r][jh * 4 + 0] * inv;
            w.y = o_[r][jh * 4 + 1] * inv;
            w.z = o_[r][jh * 4 + 2] * inv;
            w.w = o_[r][jh * 4 + 3] * inv;
            *(float4*)(op + (size_t)il * DKH + col) = w;
        }
    }
}

// ---------------------------------------------------------------------------
extern "C" void kernel_launch(void* const* d_in, const int* in_sizes, int n_in,
                              void* d_out, int out_size)
{
    const float* key   = (const float*)d_in[0];
    const float* query = (const float*)d_in[1];
    const float* value = (const float*)d_in[2];
    const float* Wq = (const float*)d_in[4];
    const float* bq = (const float*)d_in[5];
    const float* Wk = (const float*)d_in[6];
    const float* bk = (const float*)d_in[7];
    const float* Wv = (const float*)d_in[8];
    const float* bv = (const float*)d_in[9];
    const float* Wo = (const float*)d_in[10];
    const float* bo = (const float*)d_in[11];
    float* out = (float*)d_out;

    float *gq, *gk, *gv, *go;
    __nv_bfloat16 *xh, *xl, *wh, *wl;
    cudaGetSymbolAddress((void**)&gq, g_q);
    cudaGetSymbolAddress((void**)&gk, g_k);
    cudaGetSymbolAddress((void**)&gv, g_v);
    cudaGetSymbolAddress((void**)&go, g_o);
    cudaGetSymbolAddress((void**)&xh, g_xh);
    cudaGetSymbolAddress((void**)&xl, g_xl);
    cudaGetSymbolAddress((void**)&wh, g_wh);
    cudaGetSymbolAddress((void**)&wl, g_wl);

    cudaFuncSetAttribute(gemm_bf16x3,
                         cudaFuncAttributeMaxDynamicSharedMemorySize, GEMM_SMEM);
    const int attn_smem = ATTN_SMEM_FLOATS * (int)sizeof(float);   // 200704 B
    cudaFuncSetAttribute(attn_kernel,
                         cudaFuncAttributeMaxDynamicSharedMemorySize, attn_smem);

    const int nx4 = MROWS * DMODEL / 4;
    const int nw4 = DMODEL * DMODEL / 4;
    dim3 gfp32(DMODEL / 128, MROWS / 128);       // (16, 32)
    dim3 gmma(DMODEL / GB_BN, MROWS / GB_BM);    // (16, 32)

    // Q/K projections: floor-critical -> fp32 SIMT (R1-identical numerics)
    gemm_nt_bias<<<gfp32, 256>>>(query, Wq, bq, gq);
    gemm_nt_bias<<<gfp32, 256>>>(key,   Wk, bk, gk);

    // V projection: smooth -> bf16x3 mma (direct accumulation)
    split2_bf16<<<nx4 / 256, 256>>>(value, xh, xl, nx4);
    split2_bf16<<<nw4 / 256, 256>>>(Wv, wh, wl, nw4);
    gemm_bf16x3<<<gmma, 256, GEMM_SMEM>>>(xh, xl, wh, wl, bv, gv);

    // Attention (fp32, 128-row x 128-key tiles)
    attn_kernel<<<dim3(S_LEN / 128, BATCH * NHEADS), 256, attn_smem>>>();

    // Output projection: smooth -> bf16x3 mma (direct accumulation)
    split2_bf16<<<nx4 / 256, 256>>>(go, xh, xl, nx4);
    split2_bf16<<<nw4 / 256, 256>>>(Wo, wh, wl, nw4);
    gemm_bf16x3<<<gmma, 256, GEMM_SMEM>>>(xh, xl, wh, wl, bo, out);
}

// round 15
// speedup vs baseline: 1.0834x; 1.0503x over previous
#include <cuda_runtime.h>
#include <cuda_bf16.h>
#include <math.h>
#include <stdint.h>

// Problem constants
#define S_LEN 2048
#define DMODEL 2048
#define NHEADS 16
#define DKH 128
#define BATCH 2
#define MROWS (BATCH * S_LEN)   // 4096
#define SQRT_DM 45.254833995939045f

// ---------------------------------------------------------------------------
// Scratch (__device__ globals; no allocation allowed)
// ---------------------------------------------------------------------------
__device__ float g_q[(size_t)MROWS * DMODEL];
__device__ float g_k[(size_t)MROWS * DMODEL];
__device__ float g_o[(size_t)MROWS * DMODEL];
__device__ __nv_bfloat16 g_xh[(size_t)MROWS * DMODEL];
__device__ __nv_bfloat16 g_xl[(size_t)MROWS * DMODEL];
__device__ __nv_bfloat16 g_wh[(size_t)DMODEL * DMODEL];
__device__ __nv_bfloat16 g_wl[(size_t)DMODEL * DMODEL];
// V projection output, transposed split-bf16: [bh][dk (128)][token (2048)]
__device__ __nv_bfloat16 g_vth[(size_t)32 * 128 * 2048];
__device__ __nv_bfloat16 g_vtl[(size_t)32 * 128 * 2048];

// ---------------------------------------------------------------------------
// PTX helpers (base sm_100 target safe: mma.sync / ldmatrix / cp.async only)
// ---------------------------------------------------------------------------
static __device__ __forceinline__ uint32_t smem_u32(const void* p) {
    uint32_t a;
    asm("{ .reg .u64 t; cvta.to.shared.u64 t, %1; cvt.u32.u64 %0, t; }"
        : "=r"(a) : "l"(p));
    return a;
}

#define CP_ASYNC16(saddr, gaddr) \
    asm volatile("cp.async.cg.shared.global [%0], [%1], 16;" :: "r"(saddr), "l"(gaddr))
#define CP_ASYNC_COMMIT() asm volatile("cp.async.commit_group;" ::: "memory")
#define CP_ASYNC_WAIT0()  asm volatile("cp.async.wait_group 0;" ::: "memory")
#define CP_ASYNC_WAIT1()  asm volatile("cp.async.wait_group 1;" ::: "memory")

static __device__ __forceinline__ void ldsm_x4(uint32_t (&r)[4], uint32_t addr) {
    asm volatile("ldmatrix.sync.aligned.m8n8.x4.shared.b16 {%0,%1,%2,%3}, [%4];"
                 : "=r"(r[0]), "=r"(r[1]), "=r"(r[2]), "=r"(r[3]) : "r"(addr));
}
static __device__ __forceinline__ void mma_bf16(float (&d)[4],
                                                const uint32_t (&a)[4],
                                                const uint32_t b0, const uint32_t b1) {
    asm volatile("mma.sync.aligned.m16n8k16.row.col.f32.bf16.bf16.f32 "
                 "{%0,%1,%2,%3}, {%4,%5,%6,%7}, {%8,%9}, {%0,%1,%2,%3};"
                 : "+f"(d[0]), "+f"(d[1]), "+f"(d[2]), "+f"(d[3])
                 : "r"(a[0]), "r"(a[1]), "r"(a[2]), "r"(a[3]),
                   "r"(b0), "r"(b1));
}

// ---------------------------------------------------------------------------
// fp32 SIMT GEMM (R1, measured-passing): C = A @ W^T + bias
// Floor-critical Q/K projections. UNCHANGED numerics.
// ---------------------------------------------------------------------------
__global__ __launch_bounds__(256) void gemm_nt_bias(
    const float* __restrict__ A, const float* __restrict__ W,
    const float* __restrict__ bias, float* __restrict__ C)
{
    const int K = DMODEL;
    const int N = DMODEL;

    __shared__ float As[16][132];
    __shared__ float Bs[16][132];

    const int tid = threadIdx.x;
    const int tr  = tid >> 4;
    const int tc  = tid & 15;
    const int bm  = blockIdx.y << 7;
    const int bn  = blockIdx.x << 7;

    const int lr = tid >> 2;
    const int lk = (tid & 3) << 2;

    const float* Ar0 = A + (size_t)(bm + lr) * K + lk;
    const float* Ar1 = A + (size_t)(bm + 64 + lr) * K + lk;
    const float* Wr0 = W + (size_t)(bn + lr) * K + lk;
    const float* Wr1 = W + (size_t)(bn + 64 + lr) * K + lk;

    float acc[8][8];
#pragma unroll
    for (int i = 0; i < 8; i++)
#pragma unroll
        for (int j = 0; j < 8; j++) acc[i][j] = 0.f;

    float4 pa0 = *(const float4*)(Ar0);
    float4 pa1 = *(const float4*)(Ar1);
    float4 pb0 = *(const float4*)(Wr0);
    float4 pb1 = *(const float4*)(Wr1);

    for (int kt = 0; kt < K; kt += 16) {
        As[lk + 0][lr] = pa0.x; As[lk + 1][lr] = pa0.y;
        As[lk + 2][lr] = pa0.z; As[lk + 3][lr] = pa0.w;
        As[lk + 0][64 + lr] = pa1.x; As[lk + 1][64 + lr] = pa1.y;
        As[lk + 2][64 + lr] = pa1.z; As[lk + 3][64 + lr] = pa1.w;
        Bs[lk + 0][lr] = pb0.x; Bs[lk + 1][lr] = pb0.y;
        Bs[lk + 2][lr] = pb0.z; Bs[lk + 3][lr] = pb0.w;
        Bs[lk + 0][64 + lr] = pb1.x; Bs[lk + 1][64 + lr] = pb1.y;
        Bs[lk + 2][64 + lr] = pb1.z; Bs[lk + 3][64 + lr] = pb1.w;
        __syncthreads();

        if (kt + 16 < K) {
            pa0 = *(const float4*)(Ar0 + kt + 16);
            pa1 = *(const float4*)(Ar1 + kt + 16);
            pb0 = *(const float4*)(Wr0 + kt + 16);
            pb1 = *(const float4*)(Wr1 + kt + 16);
        }

#pragma unroll
        for (int k = 0; k < 16; k++) {
            float4 x0 = *(const float4*)&As[k][tr << 2];
            float4 x1 = *(const float4*)&As[k][64 + (tr << 2)];
            float4 y0 = *(const float4*)&Bs[k][tc << 2];
            float4 y1 = *(const float4*)&Bs[k][64 + (tc << 2)];
            float av[8] = {x0.x, x0.y, x0.z, x0.w, x1.x, x1.y, x1.z, x1.w};
            float bv[8] = {y0.x, y0.y, y0.z, y0.w, y1.x, y1.y, y1.z, y1.w};
#pragma unroll
            for (int i = 0; i < 8; i++)
#pragma unroll
                for (int j = 0; j < 8; j++) acc[i][j] += av[i] * bv[j];
        }
        __syncthreads();
    }

#pragma unroll
    for (int i = 0; i < 8; i++) {
        int row = bm + ((i < 4) ? ((tr << 2) + i) : (64 + (tr << 2) + i - 4));
#pragma unroll
        for (int jh = 0; jh < 2; jh++) {
            int col = bn + (jh ? (64 + (tc << 2)) : (tc << 2));
            float4 r;
            r.x = acc[i][jh * 4 + 0] + __ldg(&bias[col + 0]);
            r.y = acc[i][jh * 4 + 1] + __ldg(&bias[col + 1]);
            r.z = acc[i][jh * 4 + 2] + __ldg(&bias[col + 2]);
            r.w = acc[i][jh * 4 + 3] + __ldg(&bias[col + 3]);
            *(float4*)(C + (size_t)row * N + col) = r;
        }
    }
}

// ---------------------------------------------------------------------------
// Split fp32 -> (bf16 hi, bf16 lo); residual exact in fp32.
// ---------------------------------------------------------------------------
__global__ __launch_bounds__(256) void split2_bf16(
    const float* __restrict__ x,
    __nv_bfloat16* __restrict__ h, __nv_bfloat16* __restrict__ l, int n4)
{
    int i = blockIdx.x * blockDim.x + threadIdx.x;
    if (i >= n4) return;
    float4 v = ((const float4*)x)[i];
    float vv[4] = {v.x, v.y, v.z, v.w};
    __nv_bfloat16 hh[4], ll[4];
#pragma unroll
    for (int j = 0; j < 4; j++) {
        hh[j] = __float2bfloat16(vv[j]);
        ll[j] = __float2bfloat16(vv[j] - __bfloat162float(hh[j]));
    }
    __nv_bfloat162* hp = (__nv_bfloat162*)h + 2 * (size_t)i;
    __nv_bfloat162* lp = (__nv_bfloat162*)l + 2 * (size_t)i;
    hp[0] = __halves2bfloat162(hh[0], hh[1]);
    hp[1] = __halves2bfloat162(hh[2], hh[3]);
    lp[0] = __halves2bfloat162(ll[0], ll[1]);
    lp[1] = __halves2bfloat162(ll[2], ll[3]);
}

// ---------------------------------------------------------------------------
// mma.sync bf16x3 GEMM (hh + hl + lh), direct accumulation (smooth paths).
// OUT_MODE 0: fp32 C (O projection).
// OUT_MODE 1: transposed split-bf16 output g_vt[bh][dk][token] (V projection),
//   using the bug-faithful no-transpose reshape mapping:
//   s = row & 2047; h = s >> 7; token j = (s & 127)*16 + (col >> 7); dk = col & 127.
// ---------------------------------------------------------------------------
#define GB_BM 128
#define GB_BN 128
#define GB_BK 32
#define LDP 40
#define TILE_ELEMS (128 * LDP)
#define STG_BYTES (4 * TILE_ELEMS * 2)
#define GEMM_SMEM (2 * STG_BYTES)         // 81920 B
#define NCHUNK (DMODEL / GB_BK)           // 64

template<int OUT_MODE>
__global__ __launch_bounds__(256, 2) void gemm_bf16x3(
    const __nv_bfloat16* __restrict__ Ah, const __nv_bfloat16* __restrict__ Al,
    const __nv_bfloat16* __restrict__ Bh, const __nv_bfloat16* __restrict__ Bl,
    const float* __restrict__ bias, float* __restrict__ C,
    __nv_bfloat16* __restrict__ Th, __nv_bfloat16* __restrict__ Tl)
{
    extern __shared__ __nv_bfloat16 smem[];
    const uint32_t sbase = smem_u32(smem);

    const int tid  = threadIdx.x;
    const int wid  = tid >> 5;
    const int lane = tid & 31;
    const int wm   = wid & 1;
    const int wn   = wid >> 1;
    const int bm   = blockIdx.y * GB_BM;
    const int bn   = blockIdx.x * GB_BN;

    float sum[4][4][4];
#pragma unroll
    for (int m = 0; m < 4; m++)
#pragma unroll
        for (int n = 0; n < 4; n++)
#pragma unroll
            for (int e = 0; e < 4; e++) sum[m][n][e] = 0.f;

    const int li0 = tid * 2;

    auto prefetch = [&](int chunk) {
        const uint32_t st = sbase + (uint32_t)(chunk & 1) * STG_BYTES;
        const int kk = chunk * GB_BK;
#pragma unroll
        for (int i = 0; i < 2; i++) {
            int idx = li0 + i;
            int r = idx >> 2;
            int c = (idx & 3) * 8;
            uint32_t soff = (uint32_t)(r * LDP + c) * 2;
            size_t ga = (size_t)(bm + r) * DMODEL + kk + c;
            size_t gb = (size_t)(bn + r) * DMODEL + kk + c;
            CP_ASYNC16(st + soff, Ah + ga);
            CP_ASYNC16(st + (uint32_t)TILE_ELEMS * 2 + soff, Al + ga);
            CP_ASYNC16(st + (uint32_t)(2 * TILE_ELEMS) * 2 + soff, Bh + gb);
            CP_ASYNC16(st + (uint32_t)(3 * TILE_ELEMS) * 2 + soff, Bl + gb);
        }
    };

    prefetch(0);
    CP_ASYNC_COMMIT();

    const int a_row = wm * 64 + (lane & 15);
    const int a_colh = (lane >> 4) * 8;
    const int bp_row = wn * 32 + ((lane >> 4) & 1) * 8 + (lane & 7);
    const int bp_colh = ((lane >> 3) & 1) * 8;

    for (int chunk = 0; chunk < NCHUNK; chunk++) {
        if (chunk + 1 < NCHUNK) {
            prefetch(chunk + 1);
            CP_ASYNC_COMMIT();
            CP_ASYNC_WAIT1();
        } else {
            CP_ASYNC_WAIT0();
        }
        __syncthreads();

        const uint32_t st = sbase + (uint32_t)(chunk & 1) * STG_BYTES;

#pragma unroll
        for (int ks = 0; ks < GB_BK; ks += 16) {
            uint32_t ah[4][4], al[4][4], bh[4][2], bl[4][2];
#pragma unroll
            for (int m = 0; m < 4; m++) {
                uint32_t off = (uint32_t)((a_row + m * 16) * LDP + ks + a_colh) * 2;
                ldsm_x4(ah[m], st + off);
                ldsm_x4(al[m], st + (uint32_t)TILE_ELEMS * 2 + off);
            }
#pragma unroll
            for (int np = 0; np < 2; np++) {
                uint32_t off = (uint32_t)((bp_row + np * 16) * LDP + ks + bp_colh) * 2;
                uint32_t rh[4], rl[4];
                ldsm_x4(rh, st + (uint32_t)(2 * TILE_ELEMS) * 2 + off);
                ldsm_x4(rl, st + (uint32_t)(3 * TILE_ELEMS) * 2 + off);
                bh[2 * np + 0][0] = rh[0]; bh[2 * np + 0][1] = rh[1];
                bh[2 * np + 1][0] = rh[2]; bh[2 * np + 1][1] = rh[3];
                bl[2 * np + 0][0] = rl[0]; bl[2 * np + 0][1] = rl[1];
                bl[2 * np + 1][0] = rl[2]; bl[2 * np + 1][1] = rl[3];
            }
#pragma unroll
            for (int m = 0; m < 4; m++)
#pragma unroll
                for (int n = 0; n < 4; n++) {
                    mma_bf16(sum[m][n], ah[m], bh[n][0], bh[n][1]);
                    mma_bf16(sum[m][n], ah[m], bl[n][0], bl[n][1]);
                    mma_bf16(sum[m][n], al[m], bh[n][0], bh[n][1]);
                }
        }
        __syncthreads();
    }

#pragma unroll
    for (int m = 0; m < 4; m++) {
        int row0 = bm + wm * 64 + m * 16 + (lane >> 2);
#pragma unroll
        for (int n = 0; n < 4; n++) {
            int col = bn + wn * 32 + n * 8 + (lane & 3) * 2;
            float2 bb = __ldg((const float2*)&bias[col]);
            float v00 = sum[m][n][0] + bb.x, v01 = sum[m][n][1] + bb.y;
            float v10 = sum[m][n][2] + bb.x, v11 = sum[m][n][3] + bb.y;
            if (OUT_MODE == 0) {
                *(float2*)(C + (size_t)row0 * DMODEL + col) = make_float2(v00, v01);
                *(float2*)(C + (size_t)(row0 + 8) * DMODEL + col) = make_float2(v10, v11);
            } else {
                // CORRECT no-transpose-reshape mapping:
                // s = row within batch; head from token row, not column.
                int b = row0 >> 11, s = row0 & 2047;
                int h = s >> 7;
                int jj = ((s & 127) << 4) + (col >> 7);   // slab token
                int dk = col & 127;
                size_t tb = ((size_t)(b * 16 + h) * 128 + dk) * 2048 + jj;
                // e=0:(row0,col)  e=1:(row0,col+1)->dk+1:+2048
                // e=2:(row0+8,col)->j+128:+128   e=3: both
#pragma unroll
                for (int e = 0; e < 4; e++) {
                    float v = (e == 0) ? v00 : (e == 1) ? v01 : (e == 2) ? v10 : v11;
                    size_t idx = tb + ((e & 1) ? 2048 : 0) + ((e >= 2) ? 128 : 0);
                    __nv_bfloat16 hi = __float2bfloat16(v);
                    Th[idx] = hi;
                    Tl[idx] = __float2bfloat16(v - __bfloat162float(hi));
                }
            }
        }
    }
}

// ---------------------------------------------------------------------------
// Fused causal attention v4b: S/softmax in fp32 (R10-identical scores),
// PV on mma.sync bf16x3. 128-row Q blocks x 64-key tiles.
// ---------------------------------------------------------------------------
#define AQ_LD 132
#define AK_LD 68
#define AV_LD 72
#define AP_LD 72
#define AOFF_QS 0
#define AOFF_KS (AOFF_QS + 128 * AQ_LD * 4)
#define AOFF_VSH (AOFF_KS + 128 * AK_LD * 4)
#define AOFF_VSL (AOFF_VSH + 128 * AV_LD * 2)
#define AOFF_PSH (AOFF_VSL + 128 * AV_LD * 2)
#define AOFF_PSL (AOFF_PSH + 128 * AP_LD * 2)
#define AOFF_FROW (AOFF_PSL + 128 * AP_LD * 2)
#define AOFF_LROW (AOFF_FROW + 128 * 4)
#define ATTN_SMEM (AOFF_LROW + 128 * 4)            // 177152 B

__global__ __launch_bounds__(256) void attn_kernel()
{
    extern __shared__ char smraw[];
    float* Qs = (float*)(smraw + AOFF_QS);
    float* Ks = (float*)(smraw + AOFF_KS);
    __nv_bfloat16* Vsh = (__nv_bfloat16*)(smraw + AOFF_VSH);
    __nv_bfloat16* Vsl = (__nv_bfloat16*)(smraw + AOFF_VSL);
    __nv_bfloat16* Psh = (__nv_bfloat16*)(smraw + AOFF_PSH);
    __nv_bfloat16* Psl = (__nv_bfloat16*)(smraw + AOFF_PSL);
    float* f_row = (float*)(smraw + AOFF_FROW);
    float* l_row = (float*)(smraw + AOFF_LROW);

    const int tid  = threadIdx.x;
    const int tr   = tid >> 4;
    const int tc   = tid & 15;
    const int wid  = tid >> 5;
    const int lane = tid & 31;
    const int wm   = wid & 1;
    const int wn   = wid >> 1;
    const int qb   = gridDim.x - 1 - blockIdx.x;
    const int bh   = blockIdx.y;

    const size_t base = (size_t)bh * (S_LEN * DKH);
    const float* qp = g_q + base + (size_t)qb * 128 * DKH;
    const float* kp0 = g_k + base;
    const __nv_bfloat16* vth = g_vth + (size_t)bh * 128 * 2048;
    const __nv_bfloat16* vtl = g_vtl + (size_t)bh * 128 * 2048;

    const uint32_t psh_b = smem_u32(Psh);
    const uint32_t psl_b = smem_u32(Psl);
    const uint32_t vsh_b = smem_u32(Vsh);
    const uint32_t vsl_b = smem_u32(Vsl);

#pragma unroll
    for (int it = 0; it < 16; it++) {
        int slot = tid + (it << 8);
        int i  = slot >> 5;
        int d0 = (slot & 31) << 2;
        float4 v = *(const float4*)(qp + (size_t)i * DKH + d0);
        Qs[(d0 + 0) * AQ_LD + i] = v.x;
        Qs[(d0 + 1) * AQ_LD + i] = v.y;
        Qs[(d0 + 2) * AQ_LD + i] = v.z;
        Qs[(d0 + 3) * AQ_LD + i] = v.w;
    }

    float m_[8], l_[8];
    float of[4][4][4];
#pragma unroll
    for (int r = 0; r < 8; r++) { m_[r] = -INFINITY; l_[r] = 0.f; }
#pragma unroll
    for (int mt = 0; mt < 4; mt++)
#pragma unroll
        for (int nt = 0; nt < 4; nt++)
#pragma unroll
            for (int e = 0; e < 4; e++) of[mt][nt][e] = 0.f;

    const int a_row  = wm * 64 + (lane & 15);
    const int a_colh = (lane >> 4) * 8;
    const int bp_row  = wn * 32 + ((lane >> 4) & 1) * 8 + (lane & 7);
    const int bp_colh = ((lane >> 3) & 1) * 8;

    const int nkb = 2 * qb + 2;
    for (int kb = 0; kb < nkb; kb++) {
        __syncthreads();

        const float* kp = kp0 + (size_t)kb * 64 * DKH;
#pragma unroll
        for (int it = 0; it < 8; it++) {
            int slot = tid + (it << 8);
            int j  = slot >> 5;
            int d0 = (slot & 31) << 2;
            float4 v = *(const float4*)(kp + (size_t)j * DKH + d0);
            Ks[(d0 + 0) * AK_LD + j] = v.x;
            Ks[(d0 + 1) * AK_LD + j] = v.y;
            Ks[(d0 + 2) * AK_LD + j] = v.z;
            Ks[(d0 + 3) * AK_LD + j] = v.w;
        }
#pragma unroll
        for (int it = 0; it < 4; it++) {
            int slot = tid + (it << 8);
            int d  = slot >> 3;
            int j0 = (slot & 7) << 3;
            size_t gsrc = (size_t)d * 2048 + (size_t)kb * 64 + j0;
            *(uint4*)(Vsh + d * AV_LD + j0) = *(const uint4*)(vth + gsrc);
            *(uint4*)(Vsl + d * AV_LD + j0) = *(const uint4*)(vtl + gsrc);
        }
        __syncthreads();

        float sacc[8][4];
#pragma unroll
        for (int r = 0; r < 8; r++)
#pragma unroll
            for (int c = 0; c < 4; c++) sacc[r][c] = 0.f;

#pragma unroll 4
        for (int d = 0; d < 128; d++) {
            float4 x0 = *(const float4*)(Qs + d * AQ_LD + (tr << 2));
            float4 x1 = *(const float4*)(Qs + d * AQ_LD + 64 + (tr << 2));
            float4 y  = *(const float4*)(Ks + d * AK_LD + (tc << 2));
            float av[8] = {x0.x, x0.y, x0.z, x0.w, x1.x, x1.y, x1.z, x1.w};
            float bv[4] = {y.x, y.y, y.z, y.w};
#pragma unroll
            for (int r = 0; r < 8; r++)
#pragma unroll
                for (int c = 0; c < 4; c++) sacc[r][c] += av[r] * bv[c];
        }

        const int gj0 = kb * 64 + (tc << 2);
#pragma unroll
        for (int r = 0; r < 8; r++) {
            int il = (r < 4) ? ((tr << 2) + r) : (64 + (tr << 2) + r - 4);
            int gi = qb * 128 + il;
            float mrow = -INFINITY;
#pragma unroll
            for (int c = 0; c < 4; c++) {
                float s_ = floorf(sacc[r][c] / SQRT_DM);
                if (gj0 + c > gi) s_ = -INFINITY;
                sacc[r][c] = s_;
                mrow = fmaxf(mrow, s_);
            }
#pragma unroll
            for (int off = 8; off >= 1; off >>= 1)
                mrow = fmaxf(mrow, __shfl_xor_sync(0xffffffffu, mrow, off));

            float mnew = fmaxf(m_[r], mrow);
            float f = __expf(m_[r] - mnew);
            m_[r] = mnew;

            float rs = 0.f;
            float pv[4];
#pragma unroll
            for (int c = 0; c < 4; c++) {
                float p = __expf(sacc[r][c] - mnew);
                rs += p;
                pv[c] = p;
            }
            __nv_bfloat16 h0 = __float2bfloat16(pv[0]);
            __nv_bfloat16 h1 = __float2bfloat16(pv[1]);
            __nv_bfloat16 h2 = __float2bfloat16(pv[2]);
            __nv_bfloat16 h3 = __float2bfloat16(pv[3]);
            __nv_bfloat162* ph = (__nv_bfloat162*)(Psh + il * AP_LD + (tc << 2));
            __nv_bfloat162* pl = (__nv_bfloat162*)(Psl + il * AP_LD + (tc << 2));
            ph[0] = __halves2bfloat162(h0, h1);
            ph[1] = __halves2bfloat162(h2, h3);
            pl[0] = __halves2bfloat162(
                __float2bfloat16(pv[0] - __bfloat162float(h0)),
                __float2bfloat16(pv[1] - __bfloat162float(h1)));
            pl[1] = __halves2bfloat162(
                __float2bfloat16(pv[2] - __bfloat162float(h2)),
                __float2bfloat16(pv[3] - __bfloat162float(h3)));

#pragma unroll
            for (int off = 8; off >= 1; off >>= 1)
                rs += __shfl_xor_sync(0xffffffffu, rs, off);
            l_[r] = l_[r] * f + rs;
            if (tc == 0) f_row[il] = f;
        }
        __syncthreads();

#pragma unroll
        for (int mt = 0; mt < 4; mt++) {
            int r0 = wm * 64 + mt * 16 + (lane >> 2);
            float f0 = f_row[r0];
            float f1 = f_row[r0 + 8];
#pragma unroll
            for (int nt = 0; nt < 4; nt++) {
                of[mt][nt][0] *= f0; of[mt][nt][1] *= f0;
                of[mt][nt][2] *= f1; of[mt][nt][3] *= f1;
            }
        }
#pragma unroll
        for (int kt = 0; kt < 4; kt++) {
            uint32_t ah[4][4], al[4][4], bhf[4][2], blf[4][2];
#pragma unroll
            for (int mt = 0; mt < 4; mt++) {
                uint32_t off = (uint32_t)((a_row + mt * 16) * AP_LD + kt * 16 + a_colh) * 2;
                ldsm_x4(ah[mt], psh_b + off);
                ldsm_x4(al[mt], psl_b + off);
            }
#pragma unroll
            for (int np = 0; np < 2; np++) {
                uint32_t off = (uint32_t)((bp_row + np * 16) * AV_LD + kt * 16 + bp_colh) * 2;
                uint32_t rh[4], rl[4];
                ldsm_x4(rh, vsh_b + off);
                ldsm_x4(rl, vsl_b + off);
                bhf[2 * np + 0][0] = rh[0]; bhf[2 * np + 0][1] = rh[1];
                bhf[2 * np + 1][0] = rh[2]; bhf[2 * np + 1][1] = rh[3];
                blf[2 * np + 0][0] = rl[0]; blf[2 * np + 0][1] = rl[1];
                blf[2 * np + 1][0] = rl[2]; blf[2 * np + 1][1] = rl[3];
            }
#pragma unroll
            for (int mt = 0; mt < 4; mt++)
#pragma unroll
                for (int nt = 0; nt < 4; nt++) {
                    mma_bf16(of[mt][nt], ah[mt], bhf[nt][0], bhf[nt][1]);
                    mma_bf16(of[mt][nt], ah[mt], blf[nt][0], blf[nt][1]);
                    mma_bf16(of[mt][nt], al[mt], bhf[nt][0], bhf[nt][1]);
                }
        }
    }

    if (tc == 0) {
#pragma unroll
        for (int r = 0; r < 8; r++) {
            int il = (r < 4) ? ((tr << 2) + r) : (64 + (tr << 2) + r - 4);
            l_row[il] = l_[r];
        }
    }
    __syncthreads();

    float* op = g_o + base + (size_t)qb * 128 * DKH;
#pragma unroll
    for (int mt = 0; mt < 4; mt++) {
        int r0 = wm * 64 + mt * 16 + (lane >> 2);
        float inv0 = 1.0f / l_row[r0];
        float inv1 = 1.0f / l_row[r0 + 8];
#pragma unroll
        for (int nt = 0; nt < 4; nt++) {
            int col = wn * 32 + nt * 8 + (lane & 3) * 2;
            *(float2*)(op + (size_t)r0 * DKH + col) =
                make_float2(of[mt][nt][0] * inv0, of[mt][nt][1] * inv0);
            *(float2*)(op + (size_t)(r0 + 8) * DKH + col) =
                make_float2(of[mt][nt][2] * inv1, of[mt][nt][3] * inv1);
        }
    }
}

// ---------------------------------------------------------------------------
extern "C" void kernel_launch(void* const* d_in, const int* in_sizes, int n_in,
                              void* d_out, int out_size)
{
    const float* key   = (const float*)d_in[0];
    const float* query = (const float*)d_in[1];
    const float* value = (const float*)d_in[2];
    const float* Wq = (const float*)d_in[4];
    const float* bq = (const float*)d_in[5];
    const float* Wk = (const float*)d_in[6];
    const float* bk = (const float*)d_in[7];
    const float* Wv = (const float*)d_in[8];
    const float* bv = (const float*)d_in[9];
    const float* Wo = (const float*)d_in[10];
    const float* bo = (const float*)d_in[11];
    float* out = (float*)d_out;

    float *gq, *gk, *go;
    __nv_bfloat16 *xh, *xl, *wh, *wl, *vth, *vtl;
    cudaGetSymbolAddress((void**)&gq, g_q);
    cudaGetSymbolAddress((void**)&gk, g_k);
    cudaGetSymbolAddress((void**)&go, g_o);
    cudaGetSymbolAddress((void**)&xh, g_xh);
    cudaGetSymbolAddress((void**)&xl, g_xl);
    cudaGetSymbolAddress((void**)&wh, g_wh);
    cudaGetSymbolAddress((void**)&wl, g_wl);
    cudaGetSymbolAddress((void**)&vth, g_vth);
    cudaGetSymbolAddress((void**)&vtl, g_vtl);

    cudaFuncSetAttribute(gemm_bf16x3<0>,
                         cudaFuncAttributeMaxDynamicSharedMemorySize, GEMM_SMEM);
    cudaFuncSetAttribute(gemm_bf16x3<1>,
                         cudaFuncAttributeMaxDynamicSharedMemorySize, GEMM_SMEM);
    cudaFuncSetAttribute(attn_kernel,
                         cudaFuncAttributeMaxDynamicSharedMemorySize, ATTN_SMEM);

    const int nx4 = MROWS * DMODEL / 4;
    const int nw4 = DMODEL * DMODEL / 4;
    dim3 gfp32(DMODEL / 128, MROWS / 128);       // (16, 32)
    dim3 gmma(DMODEL / GB_BN, MROWS / GB_BM);    // (16, 32)

    // Q/K projections: floor-critical -> fp32 SIMT (R1-identical numerics)
    gemm_nt_bias<<<gfp32, 256>>>(query, Wq, bq, gq);
    gemm_nt_bias<<<gfp32, 256>>>(key,   Wk, bk, gk);

    // V projection: smooth -> bf16x3 mma, transposed split-bf16 output
    split2_bf16<<<nx4 / 256, 256>>>(value, xh, xl, nx4);
    split2_bf16<<<nw4 / 256, 256>>>(Wv, wh, wl, nw4);
    gemm_bf16x3<1><<<gmma, 256, GEMM_SMEM>>>(xh, xl, wh, wl, bv, nullptr, vth, vtl);

    // Attention: fp32 S/softmax (R10 scores) + mma PV
    attn_kernel<<<dim3(S_LEN / 128, BATCH * NHEADS), 256, ATTN_SMEM>>>();

    // Output projection: smooth -> bf16x3 mma, fp32 output
    split2_bf16<<<nx4 / 256, 256>>>(go, xh, xl, nx4);
    split2_bf16<<<nw4 / 256, 256>>>(Wo, wh, wl, nw4);
    gemm_bf16x3<0><<<gmma, 256, GEMM_SMEM>>>(xh, xl, wh, wl, bo, out, nullptr, nullptr);
}

// round 16
// speedup vs baseline: 1.1623x; 1.0728x over previous
#include <cuda_runtime.h>
#include <cuda_bf16.h>
#include <math.h>
#include <stdint.h>

// Problem constants
#define S_LEN 2048
#define DMODEL 2048
#define NHEADS 16
#define DKH 128
#define BATCH 2
#define MROWS (BATCH * S_LEN)   // 4096
#define SQRT_DM 45.254833995939045f

// ---------------------------------------------------------------------------
// Scratch (__device__ globals; no allocation allowed)
// ---------------------------------------------------------------------------
__device__ float g_q[(size_t)MROWS * DMODEL];
__device__ float g_k[(size_t)MROWS * DMODEL];
__device__ __nv_bfloat16 g_xh[(size_t)MROWS * DMODEL];
__device__ __nv_bfloat16 g_xl[(size_t)MROWS * DMODEL];
__device__ __nv_bfloat16 g_wh[(size_t)DMODEL * DMODEL];
__device__ __nv_bfloat16 g_wl[(size_t)DMODEL * DMODEL];
// V projection output, transposed split-bf16: [bh][dk (128)][token (2048)]
__device__ __nv_bfloat16 g_vth[(size_t)32 * 128 * 2048];
__device__ __nv_bfloat16 g_vtl[(size_t)32 * 128 * 2048];

// ---------------------------------------------------------------------------
// PTX helpers (base sm_100 target safe: mma.sync / ldmatrix / cp.async only)
// ---------------------------------------------------------------------------
static __device__ __forceinline__ uint32_t smem_u32(const void* p) {
    uint32_t a;
    asm("{ .reg .u64 t; cvta.to.shared.u64 t, %1; cvt.u32.u64 %0, t; }"
        : "=r"(a) : "l"(p));
    return a;
}

#define CP_ASYNC16(saddr, gaddr) \
    asm volatile("cp.async.cg.shared.global [%0], [%1], 16;" :: "r"(saddr), "l"(gaddr))
#define CP_ASYNC_COMMIT() asm volatile("cp.async.commit_group;" ::: "memory")
#define CP_ASYNC_WAIT0()  asm volatile("cp.async.wait_group 0;" ::: "memory")
#define CP_ASYNC_WAIT1()  asm volatile("cp.async.wait_group 1;" ::: "memory")

static __device__ __forceinline__ void ldsm_x4(uint32_t (&r)[4], uint32_t addr) {
    asm volatile("ldmatrix.sync.aligned.m8n8.x4.shared.b16 {%0,%1,%2,%3}, [%4];"
                 : "=r"(r[0]), "=r"(r[1]), "=r"(r[2]), "=r"(r[3]) : "r"(addr));
}
static __device__ __forceinline__ void mma_bf16(float (&d)[4],
                                                const uint32_t (&a)[4],
                                                const uint32_t b0, const uint32_t b1) {
    asm volatile("mma.sync.aligned.m16n8k16.row.col.f32.bf16.bf16.f32 "
                 "{%0,%1,%2,%3}, {%4,%5,%6,%7}, {%8,%9}, {%0,%1,%2,%3};"
                 : "+f"(d[0]), "+f"(d[1]), "+f"(d[2]), "+f"(d[3])
                 : "r"(a[0]), "r"(a[1]), "r"(a[2]), "r"(a[3]),
                   "r"(b0), "r"(b1));
}

// ---------------------------------------------------------------------------
// fp32 SIMT GEMM, DUAL (Q and K in one launch via blockIdx.z) with
// double-buffered smem (one barrier per k-chunk). Per-thread FMA order is
// BIT-IDENTICAL to the measured-passing R1 kernel.
// ---------------------------------------------------------------------------
__global__ __launch_bounds__(256) void gemm_nt_bias_dual(
    const float* __restrict__ A0, const float* __restrict__ A1,
    const float* __restrict__ W0, const float* __restrict__ W1,
    const float* __restrict__ b0, const float* __restrict__ b1,
    float* __restrict__ C0, float* __restrict__ C1)
{
    const int K = DMODEL;
    const int N = DMODEL;

    const float* A    = blockIdx.z ? A1 : A0;
    const float* W    = blockIdx.z ? W1 : W0;
    const float* bias = blockIdx.z ? b1 : b0;
    float*       C    = blockIdx.z ? C1 : C0;

    __shared__ float As[2][16][132];
    __shared__ float Bs[2][16][132];

    const int tid = threadIdx.x;
    const int tr  = tid >> 4;
    const int tc  = tid & 15;
    const int bm  = blockIdx.y << 7;
    const int bn  = blockIdx.x << 7;

    const int lr = tid >> 2;
    const int lk = (tid & 3) << 2;

    const float* Ar0 = A + (size_t)(bm + lr) * K + lk;
    const float* Ar1 = A + (size_t)(bm + 64 + lr) * K + lk;
    const float* Wr0 = W + (size_t)(bn + lr) * K + lk;
    const float* Wr1 = W + (size_t)(bn + 64 + lr) * K + lk;

    float acc[8][8];
#pragma unroll
    for (int i = 0; i < 8; i++)
#pragma unroll
        for (int j = 0; j < 8; j++) acc[i][j] = 0.f;

    // chunk 0 -> stage 0
    {
        float4 pa0 = *(const float4*)(Ar0);
        float4 pa1 = *(const float4*)(Ar1);
        float4 pb0 = *(const float4*)(Wr0);
        float4 pb1 = *(const float4*)(Wr1);
        As[0][lk + 0][lr] = pa0.x; As[0][lk + 1][lr] = pa0.y;
        As[0][lk + 2][lr] = pa0.z; As[0][lk + 3][lr] = pa0.w;
        As[0][lk + 0][64 + lr] = pa1.x; As[0][lk + 1][64 + lr] = pa1.y;
        As[0][lk + 2][64 + lr] = pa1.z; As[0][lk + 3][64 + lr] = pa1.w;
        Bs[0][lk + 0][lr] = pb0.x; Bs[0][lk + 1][lr] = pb0.y;
        Bs[0][lk + 2][lr] = pb0.z; Bs[0][lk + 3][lr] = pb0.w;
        Bs[0][lk + 0][64 + lr] = pb1.x; Bs[0][lk + 1][64 + lr] = pb1.y;
        Bs[0][lk + 2][64 + lr] = pb1.z; Bs[0][lk + 3][64 + lr] = pb1.w;
    }
    __syncthreads();

    for (int kt = 0; kt < K; kt += 16) {
        const int st = (kt >> 4) & 1;

        float4 pa0, pa1, pb0, pb1;
        const bool more = (kt + 16 < K);
        if (more) {
            pa0 = *(const float4*)(Ar0 + kt + 16);
            pa1 = *(const float4*)(Ar1 + kt + 16);
            pb0 = *(const float4*)(Wr0 + kt + 16);
            pb1 = *(const float4*)(Wr1 + kt + 16);
        }

#pragma unroll
        for (int k = 0; k < 16; k++) {
            float4 x0 = *(const float4*)&As[st][k][tr << 2];
            float4 x1 = *(const float4*)&As[st][k][64 + (tr << 2)];
            float4 y0 = *(const float4*)&Bs[st][k][tc << 2];
            float4 y1 = *(const float4*)&Bs[st][k][64 + (tc << 2)];
            float av[8] = {x0.x, x0.y, x0.z, x0.w, x1.x, x1.y, x1.z, x1.w};
            float bv[8] = {y0.x, y0.y, y0.z, y0.w, y1.x, y1.y, y1.z, y1.w};
#pragma unroll
            for (int i = 0; i < 8; i++)
#pragma unroll
                for (int j = 0; j < 8; j++) acc[i][j] += av[i] * bv[j];
        }

        if (more) {
            const int sn = st ^ 1;
            As[sn][lk + 0][lr] = pa0.x; As[sn][lk + 1][lr] = pa0.y;
            As[sn][lk + 2][lr] = pa0.z; As[sn][lk + 3][lr] = pa0.w;
            As[sn][lk + 0][64 + lr] = pa1.x; As[sn][lk + 1][64 + lr] = pa1.y;
            As[sn][lk + 2][64 + lr] = pa1.z; As[sn][lk + 3][64 + lr] = pa1.w;
            Bs[sn][lk + 0][lr] = pb0.x; Bs[sn][lk + 1][lr] = pb0.y;
            Bs[sn][lk + 2][lr] = pb0.z; Bs[sn][lk + 3][lr] = pb0.w;
            Bs[sn][lk + 0][64 + lr] = pb1.x; Bs[sn][lk + 1][64 + lr] = pb1.y;
            Bs[sn][lk + 2][64 + lr] = pb1.z; Bs[sn][lk + 3][64 + lr] = pb1.w;
        }
        __syncthreads();
    }

#pragma unroll
    for (int i = 0; i < 8; i++) {
        int row = bm + ((i < 4) ? ((tr << 2) + i) : (64 + (tr << 2) + i - 4));
#pragma unroll
        for (int jh = 0; jh < 2; jh++) {
            int col = bn + (jh ? (64 + (tc << 2)) : (tc << 2));
            float4 r;
            r.x = acc[i][jh * 4 + 0] + __ldg(&bias[col + 0]);
            r.y = acc[i][jh * 4 + 1] + __ldg(&bias[col + 1]);
            r.z = acc[i][jh * 4 + 2] + __ldg(&bias[col + 2]);
            r.w = acc[i][jh * 4 + 3] + __ldg(&bias[col + 3]);
            *(float4*)(C + (size_t)row * N + col) = r;
        }
    }
}

// ---------------------------------------------------------------------------
// Split fp32 -> (bf16 hi, bf16 lo); residual exact in fp32.
// ---------------------------------------------------------------------------
__global__ __launch_bounds__(256) void split2_bf16(
    const float* __restrict__ x,
    __nv_bfloat16* __restrict__ h, __nv_bfloat16* __restrict__ l, int n4)
{
    int i = blockIdx.x * blockDim.x + threadIdx.x;
    if (i >= n4) return;
    float4 v = ((const float4*)x)[i];
    float vv[4] = {v.x, v.y, v.z, v.w};
    __nv_bfloat16 hh[4], ll[4];
#pragma unroll
    for (int j = 0; j < 4; j++) {
        hh[j] = __float2bfloat16(vv[j]);
        ll[j] = __float2bfloat16(vv[j] - __bfloat162float(hh[j]));
    }
    __nv_bfloat162* hp = (__nv_bfloat162*)h + 2 * (size_t)i;
    __nv_bfloat162* lp = (__nv_bfloat162*)l + 2 * (size_t)i;
    hp[0] = __halves2bfloat162(hh[0], hh[1]);
    hp[1] = __halves2bfloat162(hh[2], hh[3]);
    lp[0] = __halves2bfloat162(ll[0], ll[1]);
    lp[1] = __halves2bfloat162(ll[2], ll[3]);
}

// ---------------------------------------------------------------------------
// mma.sync bf16x3 GEMM (hh + hl + lh), direct accumulation (smooth paths).
// OUT_MODE 0: fp32 C (O projection).
// OUT_MODE 1: transposed split-bf16 output g_vt[bh][dk][token] (V projection).
// ---------------------------------------------------------------------------
#define GB_BM 128
#define GB_BN 128
#define GB_BK 32
#define LDP 40
#define TILE_ELEMS (128 * LDP)
#define STG_BYTES (4 * TILE_ELEMS * 2)
#define GEMM_SMEM (2 * STG_BYTES)         // 81920 B
#define NCHUNK (DMODEL / GB_BK)           // 64

template<int OUT_MODE>
__global__ __launch_bounds__(256, 2) void gemm_bf16x3(
    const __nv_bfloat16* __restrict__ Ah, const __nv_bfloat16* __restrict__ Al,
    const __nv_bfloat16* __restrict__ Bh, const __nv_bfloat16* __restrict__ Bl,
    const float* __restrict__ bias, float* __restrict__ C,
    __nv_bfloat16* __restrict__ Th, __nv_bfloat16* __restrict__ Tl)
{
    extern __shared__ __nv_bfloat16 smem[];
    const uint32_t sbase = smem_u32(smem);

    const int tid  = threadIdx.x;
    const int wid  = tid >> 5;
    const int lane = tid & 31;
    const int wm   = wid & 1;
    const int wn   = wid >> 1;
    const int bm   = blockIdx.y * GB_BM;
    const int bn   = blockIdx.x * GB_BN;

    float sum[4][4][4];
#pragma unroll
    for (int m = 0; m < 4; m++)
#pragma unroll
        for (int n = 0; n < 4; n++)
#pragma unroll
            for (int e = 0; e < 4; e++) sum[m][n][e] = 0.f;

    const int li0 = tid * 2;

    auto prefetch = [&](int chunk) {
        const uint32_t st = sbase + (uint32_t)(chunk & 1) * STG_BYTES;
        const int kk = chunk * GB_BK;
#pragma unroll
        for (int i = 0; i < 2; i++) {
            int idx = li0 + i;
            int r = idx >> 2;
            int c = (idx & 3) * 8;
            uint32_t soff = (uint32_t)(r * LDP + c) * 2;
            size_t ga = (size_t)(bm + r) * DMODEL + kk + c;
            size_t gb = (size_t)(bn + r) * DMODEL + kk + c;
            CP_ASYNC16(st + soff, Ah + ga);
            CP_ASYNC16(st + (uint32_t)TILE_ELEMS * 2 + soff, Al + ga);
            CP_ASYNC16(st + (uint32_t)(2 * TILE_ELEMS) * 2 + soff, Bh + gb);
            CP_ASYNC16(st + (uint32_t)(3 * TILE_ELEMS) * 2 + soff, Bl + gb);
        }
    };

    prefetch(0);
    CP_ASYNC_COMMIT();

    const int a_row = wm * 64 + (lane & 15);
    const int a_colh = (lane >> 4) * 8;
    const int bp_row = wn * 32 + ((lane >> 4) & 1) * 8 + (lane & 7);
    const int bp_colh = ((lane >> 3) & 1) * 8;

    for (int chunk = 0; chunk < NCHUNK; chunk++) {
        if (chunk + 1 < NCHUNK) {
            prefetch(chunk + 1);
            CP_ASYNC_COMMIT();
            CP_ASYNC_WAIT1();
        } else {
            CP_ASYNC_WAIT0();
        }
        __syncthreads();

        const uint32_t st = sbase + (uint32_t)(chunk & 1) * STG_BYTES;

#pragma unroll
        for (int ks = 0; ks < GB_BK; ks += 16) {
            uint32_t ah[4][4], al[4][4], bh[4][2], bl[4][2];
#pragma unroll
            for (int m = 0; m < 4; m++) {
                uint32_t off = (uint32_t)((a_row + m * 16) * LDP + ks + a_colh) * 2;
                ldsm_x4(ah[m], st + off);
                ldsm_x4(al[m], st + (uint32_t)TILE_ELEMS * 2 + off);
            }
#pragma unroll
            for (int np = 0; np < 2; np++) {
                uint32_t off = (uint32_t)((bp_row + np * 16) * LDP + ks + bp_colh) * 2;
                uint32_t rh[4], rl[4];
                ldsm_x4(rh, st + (uint32_t)(2 * TILE_ELEMS) * 2 + off);
                ldsm_x4(rl, st + (uint32_t)(3 * TILE_ELEMS) * 2 + off);
                bh[2 * np + 0][0] = rh[0]; bh[2 * np + 0][1] = rh[1];
                bh[2 * np + 1][0] = rh[2]; bh[2 * np + 1][1] = rh[3];
                bl[2 * np + 0][0] = rl[0]; bl[2 * np + 0][1] = rl[1];
                bl[2 * np + 1][0] = rl[2]; bl[2 * np + 1][1] = rl[3];
            }
#pragma unroll
            for (int m = 0; m < 4; m++)
#pragma unroll
                for (int n = 0; n < 4; n++) {
                    mma_bf16(sum[m][n], ah[m], bh[n][0], bh[n][1]);
                    mma_bf16(sum[m][n], ah[m], bl[n][0], bl[n][1]);
                    mma_bf16(sum[m][n], al[m], bh[n][0], bh[n][1]);
                }
        }
        __syncthreads();
    }

#pragma unroll
    for (int m = 0; m < 4; m++) {
        int row0 = bm + wm * 64 + m * 16 + (lane >> 2);
#pragma unroll
        for (int n = 0; n < 4; n++) {
            int col = bn + wn * 32 + n * 8 + (lane & 3) * 2;
            float2 bb = __ldg((const float2*)&bias[col]);
            float v00 = sum[m][n][0] + bb.x, v01 = sum[m][n][1] + bb.y;
            float v10 = sum[m][n][2] + bb.x, v11 = sum[m][n][3] + bb.y;
            if (OUT_MODE == 0) {
                *(float2*)(C + (size_t)row0 * DMODEL + col) = make_float2(v00, v01);
                *(float2*)(C + (size_t)(row0 + 8) * DMODEL + col) = make_float2(v10, v11);
            } else {
                // no-transpose-reshape mapping (measured-correct in R15):
                int b = row0 >> 11, s = row0 & 2047;
                int h = s >> 7;
                int jj = ((s & 127) << 4) + (col >> 7);
                int dk = col & 127;
                size_t tb = ((size_t)(b * 16 + h) * 128 + dk) * 2048 + jj;
#pragma unroll
                for (int e = 0; e < 4; e++) {
                    float v = (e == 0) ? v00 : (e == 1) ? v01 : (e == 2) ? v10 : v11;
                    size_t idx = tb + ((e & 1) ? 2048 : 0) + ((e >= 2) ? 128 : 0);
                    __nv_bfloat16 hi = __float2bfloat16(v);
                    Th[idx] = hi;
                    Tl[idx] = __float2bfloat16(v - __bfloat162float(hi));
                }
            }
        }
    }
}

// ---------------------------------------------------------------------------
// Fused causal attention (R15, measured-passing): fp32 S/softmax + mma PV.
// Epilogue change only: writes output directly as split bf16 (g_xh/g_xl)
// at the same flat offsets (bit-identical to split2(g_o)).
// ---------------------------------------------------------------------------
#define AQ_LD 132
#define AK_LD 68
#define AV_LD 72
#define AP_LD 72
#define AOFF_QS 0
#define AOFF_KS (AOFF_QS + 128 * AQ_LD * 4)
#define AOFF_VSH (AOFF_KS + 128 * AK_LD * 4)
#define AOFF_VSL (AOFF_VSH + 128 * AV_LD * 2)
#define AOFF_PSH (AOFF_VSL + 128 * AV_LD * 2)
#define AOFF_PSL (AOFF_PSH + 128 * AP_LD * 2)
#define AOFF_FROW (AOFF_PSL + 128 * AP_LD * 2)
#define AOFF_LROW (AOFF_FROW + 128 * 4)
#define ATTN_SMEM (AOFF_LROW + 128 * 4)            // 177152 B

__global__ __launch_bounds__(256) void attn_kernel()
{
    extern __shared__ char smraw[];
    float* Qs = (float*)(smraw + AOFF_QS);
    float* Ks = (float*)(smraw + AOFF_KS);
    __nv_bfloat16* Vsh = (__nv_bfloat16*)(smraw + AOFF_VSH);
    __nv_bfloat16* Vsl = (__nv_bfloat16*)(smraw + AOFF_VSL);
    __nv_bfloat16* Psh = (__nv_bfloat16*)(smraw + AOFF_PSH);
    __nv_bfloat16* Psl = (__nv_bfloat16*)(smraw + AOFF_PSL);
    float* f_row = (float*)(smraw + AOFF_FROW);
    float* l_row = (float*)(smraw + AOFF_LROW);

    const int tid  = threadIdx.x;
    const int tr   = tid >> 4;
    const int tc   = tid & 15;
    const int wid  = tid >> 5;
    const int lane = tid & 31;
    const int wm   = wid & 1;
    const int wn   = wid >> 1;
    const int qb   = gridDim.x - 1 - blockIdx.x;
    const int bh   = blockIdx.y;

    const size_t base = (size_t)bh * (S_LEN * DKH);
    const float* qp = g_q + base + (size_t)qb * 128 * DKH;
    const float* kp0 = g_k + base;
    const __nv_bfloat16* vth = g_vth + (size_t)bh * 128 * 2048;
    const __nv_bfloat16* vtl = g_vtl + (size_t)bh * 128 * 2048;

    const uint32_t psh_b = smem_u32(Psh);
    const uint32_t psl_b = smem_u32(Psl);
    const uint32_t vsh_b = smem_u32(Vsh);
    const uint32_t vsl_b = smem_u32(Vsl);

#pragma unroll
    for (int it = 0; it < 16; it++) {
        int slot = tid + (it << 8);
        int i  = slot >> 5;
        int d0 = (slot & 31) << 2;
        float4 v = *(const float4*)(qp + (size_t)i * DKH + d0);
        Qs[(d0 + 0) * AQ_LD + i] = v.x;
        Qs[(d0 + 1) * AQ_LD + i] = v.y;
        Qs[(d0 + 2) * AQ_LD + i] = v.z;
        Qs[(d0 + 3) * AQ_LD + i] = v.w;
    }

    float m_[8], l_[8];
    float of[4][4][4];
#pragma unroll
    for (int r = 0; r < 8; r++) { m_[r] = -INFINITY; l_[r] = 0.f; }
#pragma unroll
    for (int mt = 0; mt < 4; mt++)
#pragma unroll
        for (int nt = 0; nt < 4; nt++)
#pragma unroll
            for (int e = 0; e < 4; e++) of[mt][nt][e] = 0.f;

    const int a_row  = wm * 64 + (lane & 15);
    const int a_colh = (lane >> 4) * 8;
    const int bp_row  = wn * 32 + ((lane >> 4) & 1) * 8 + (lane & 7);
    const int bp_colh = ((lane >> 3) & 1) * 8;

    const int nkb = 2 * qb + 2;
    for (int kb = 0; kb < nkb; kb++) {
        __syncthreads();

        const float* kp = kp0 + (size_t)kb * 64 * DKH;
#pragma unroll
        for (int it = 0; it < 8; it++) {
            int slot = tid + (it << 8);
            int j  = slot >> 5;
            int d0 = (slot & 31) << 2;
            float4 v = *(const float4*)(kp + (size_t)j * DKH + d0);
            Ks[(d0 + 0) * AK_LD + j] = v.x;
            Ks[(d0 + 1) * AK_LD + j] = v.y;
            Ks[(d0 + 2) * AK_LD + j] = v.z;
            Ks[(d0 + 3) * AK_LD + j] = v.w;
        }
#pragma unroll
        for (int it = 0; it < 4; it++) {
            int slot = tid + (it << 8);
            int d  = slot >> 3;
            int j0 = (slot & 7) << 3;
            size_t gsrc = (size_t)d * 2048 + (size_t)kb * 64 + j0;
            *(uint4*)(Vsh + d * AV_LD + j0) = *(const uint4*)(vth + gsrc);
            *(uint4*)(Vsl + d * AV_LD + j0) = *(const uint4*)(vtl + gsrc);
        }
        __syncthreads();

        float sacc[8][4];
#pragma unroll
        for (int r = 0; r < 8; r++)
#pragma unroll
            for (int c = 0; c < 4; c++) sacc[r][c] = 0.f;

#pragma unroll 4
        for (int d = 0; d < 128; d++) {
            float4 x0 = *(const float4*)(Qs + d * AQ_LD + (tr << 2));
            float4 x1 = *(const float4*)(Qs + d * AQ_LD + 64 + (tr << 2));
            float4 y  = *(const float4*)(Ks + d * AK_LD + (tc << 2));
            float av[8] = {x0.x, x0.y, x0.z, x0.w, x1.x, x1.y, x1.z, x1.w};
            float bv[4] = {y.x, y.y, y.z, y.w};
#pragma unroll
            for (int r = 0; r < 8; r++)
#pragma unroll
                for (int c = 0; c < 4; c++) sacc[r][c] += av[r] * bv[c];
        }

        const int gj0 = kb * 64 + (tc << 2);
#pragma unroll
        for (int r = 0; r < 8; r++) {
            int il = (r < 4) ? ((tr << 2) + r) : (64 + (tr << 2) + r - 4);
            int gi = qb * 128 + il;
            float mrow = -INFINITY;
#pragma unroll
            for (int c = 0; c < 4; c++) {
                float s_ = floorf(sacc[r][c] / SQRT_DM);
                if (gj0 + c > gi) s_ = -INFINITY;
                sacc[r][c] = s_;
                mrow = fmaxf(mrow, s_);
            }
#pragma unroll
            for (int off = 8; off >= 1; off >>= 1)
                mrow = fmaxf(mrow, __shfl_xor_sync(0xffffffffu, mrow, off));

            float mnew = fmaxf(m_[r], mrow);
            float f = __expf(m_[r] - mnew);
            m_[r] = mnew;

            float rs = 0.f;
            float pv[4];
#pragma unroll
            for (int c = 0; c < 4; c++) {
                float p = __expf(sacc[r][c] - mnew);
                rs += p;
                pv[c] = p;
            }
            __nv_bfloat16 h0 = __float2bfloat16(pv[0]);
            __nv_bfloat16 h1 = __float2bfloat16(pv[1]);
            __nv_bfloat16 h2 = __float2bfloat16(pv[2]);
            __nv_bfloat16 h3 = __float2bfloat16(pv[3]);
            __nv_bfloat162* ph = (__nv_bfloat162*)(Psh + il * AP_LD + (tc << 2));
            __nv_bfloat162* pl = (__nv_bfloat162*)(Psl + il * AP_LD + (tc << 2));
            ph[0] = __halves2bfloat162(h0, h1);
            ph[1] = __halves2bfloat162(h2, h3);
            pl[0] = __halves2bfloat162(
                __float2bfloat16(pv[0] - __bfloat162float(h0)),
                __float2bfloat16(pv[1] - __bfloat162float(h1)));
            pl[1] = __halves2bfloat162(
                __float2bfloat16(pv[2] - __bfloat162float(h2)),
                __float2bfloat16(pv[3] - __bfloat162float(h3)));

#pragma unroll
            for (int off = 8; off >= 1; off >>= 1)
                rs += __shfl_xor_sync(0xffffffffu, rs, off);
            l_[r] = l_[r] * f + rs;
            if (tc == 0) f_row[il] = f;
        }
        __syncthreads();

#pragma unroll
        for (int mt = 0; mt < 4; mt++) {
            int r0 = wm * 64 + mt * 16 + (lane >> 2);
            float f0 = f_row[r0];
            float f1 = f_row[r0 + 8];
#pragma unroll
            for (int nt = 0; nt < 4; nt++) {
                of[mt][nt][0] *= f0; of[mt][nt][1] *= f0;
                of[mt][nt][2] *= f1; of[mt][nt][3] *= f1;
            }
        }
#pragma unroll
        for (int kt = 0; kt < 4; kt++) {
            uint32_t ah[4][4], al[4][4], bhf[4][2], blf[4][2];
#pragma unroll
            for (int mt = 0; mt < 4; mt++) {
                uint32_t off = (uint32_t)((a_row + mt * 16) * AP_LD + kt * 16 + a_colh) * 2;
                ldsm_x4(ah[mt], psh_b + off);
                ldsm_x4(al[mt], psl_b + off);
            }
#pragma unroll
            for (int np = 0; np < 2; np++) {
                uint32_t off = (uint32_t)((bp_row + np * 16) * AV_LD + kt * 16 + bp_colh) * 2;
                uint32_t rh[4], rl[4];
                ldsm_x4(rh, vsh_b + off);
                ldsm_x4(rl, vsl_b + off);
                bhf[2 * np + 0][0] = rh[0]; bhf[2 * np + 0][1] = rh[1];
                bhf[2 * np + 1][0] = rh[2]; bhf[2 * np + 1][1] = rh[3];
                blf[2 * np + 0][0] = rl[0]; blf[2 * np + 0][1] = rl[1];
                blf[2 * np + 1][0] = rl[2]; blf[2 * np + 1][1] = rl[3];
            }
#pragma unroll
            for (int mt = 0; mt < 4; mt++)
#pragma unroll
                for (int nt = 0; nt < 4; nt++) {
                    mma_bf16(of[mt][nt], ah[mt], bhf[nt][0], bhf[nt][1]);
                    mma_bf16(of[mt][nt], ah[mt], blf[nt][0], blf[nt][1]);
                    mma_bf16(of[mt][nt], al[mt], bhf[nt][0], bhf[nt][1]);
                }
        }
    }

    if (tc == 0) {
#pragma unroll
        for (int r = 0; r < 8; r++) {
            int il = (r < 4) ? ((tr << 2) + r) : (64 + (tr << 2) + r - 4);
            l_row[il] = l_[r];
        }
    }
    __syncthreads();

    // normalize + write DIRECTLY as split bf16 (same flat offsets as g_o)
    const size_t obase = base + (size_t)qb * 128 * DKH;
#pragma unroll
    for (int mt = 0; mt < 4; mt++) {
        int r0 = wm * 64 + mt * 16 + (lane >> 2);
        float inv0 = 1.0f / l_row[r0];
        float inv1 = 1.0f / l_row[r0 + 8];
#pragma unroll
        for (int nt = 0; nt < 4; nt++) {
            int col = wn * 32 + nt * 8 + (lane & 3) * 2;
            float v00 = of[mt][nt][0] * inv0, v01 = of[mt][nt][1] * inv0;
            float v10 = of[mt][nt][2] * inv1, v11 = of[mt][nt][3] * inv1;
            size_t i0 = obase + (size_t)r0 * DKH + col;
            size_t i1 = obase + (size_t)(r0 + 8) * DKH + col;
            __nv_bfloat16 h00 = __float2bfloat16(v00);
            __nv_bfloat16 h01 = __float2bfloat16(v01);
            __nv_bfloat16 h10 = __float2bfloat16(v10);
            __nv_bfloat16 h11 = __float2bfloat16(v11);
            *(__nv_bfloat162*)(g_xh + i0) = __halves2bfloat162(h00, h01);
            *(__nv_bfloat162*)(g_xh + i1) = __halves2bfloat162(h10, h11);
            *(__nv_bfloat162*)(g_xl + i0) = __halves2bfloat162(
                __float2bfloat16(v00 - __bfloat162float(h00)),
                __float2bfloat16(v01 - __bfloat162float(h01)));
            *(__nv_bfloat162*)(g_xl + i1) = __halves2bfloat162(
                __float2bfloat16(v10 - __bfloat162float(h10)),
                __float2bfloat16(v11 - __bfloat162float(h11)));
        }
    }
}

// ---------------------------------------------------------------------------
extern "C" void kernel_launch(void* const* d_in, const int* in_sizes, int n_in,
                              void* d_out, int out_size)
{
    const float* key   = (const float*)d_in[0];
    const float* query = (const float*)d_in[1];
    const float* value = (const float*)d_in[2];
    const float* Wq = (const float*)d_in[4];
    const float* bq = (const float*)d_in[5];
    const float* Wk = (const float*)d_in[6];
    const float* bk = (const float*)d_in[7];
    const float* Wv = (const float*)d_in[8];
    const float* bv = (const float*)d_in[9];
    const float* Wo = (const float*)d_in[10];
    const float* bo = (const float*)d_in[11];
    float* out = (float*)d_out;

    float *gq, *gk;
    __nv_bfloat16 *xh, *xl, *wh, *wl, *vth, *vtl;
    cudaGetSymbolAddress((void**)&gq, g_q);
    cudaGetSymbolAddress((void**)&gk, g_k);
    cudaGetSymbolAddress((void**)&xh, g_xh);
    cudaGetSymbolAddress((void**)&xl, g_xl);
    cudaGetSymbolAddress((void**)&wh, g_wh);
    cudaGetSymbolAddress((void**)&wl, g_wl);
    cudaGetSymbolAddress((void**)&vth, g_vth);
    cudaGetSymbolAddress((void**)&vtl, g_vtl);

    cudaFuncSetAttribute(gemm_bf16x3<0>,
                         cudaFuncAttributeMaxDynamicSharedMemorySize, GEMM_SMEM);
    cudaFuncSetAttribute(gemm_bf16x3<1>,
                         cudaFuncAttributeMaxDynamicSharedMemorySize, GEMM_SMEM);
    cudaFuncSetAttribute(attn_kernel,
                         cudaFuncAttributeMaxDynamicSharedMemorySize, ATTN_SMEM);

    const int nx4 = MROWS * DMODEL / 4;
    const int nw4 = DMODEL * DMODEL / 4;
    dim3 gmma(DMODEL / GB_BN, MROWS / GB_BM);    // (16, 32)

    // Q+K projections merged into one launch (wave-quantization fix)
    gemm_nt_bias_dual<<<dim3(16, 32, 2), 256>>>(query, key, Wq, Wk, bq, bk, gq, gk);

    // V projection: split inputs, then bf16x3 mma with transposed split output
    split2_bf16<<<nx4 / 256, 256>>>(value, xh, xl, nx4);
    split2_bf16<<<nw4 / 256, 256>>>(Wv, wh, wl, nw4);
    gemm_bf16x3<1><<<gmma, 256, GEMM_SMEM>>>(xh, xl, wh, wl, bv, nullptr, vth, vtl);

    // Attention: fp32 S/softmax + mma PV; writes split-bf16 output directly
    attn_kernel<<<dim3(S_LEN / 128, BATCH * NHEADS), 256, ATTN_SMEM>>>();

    // Output projection: Wo split + bf16x3 mma -> final fp32 out
    split2_bf16<<<nw4 / 256, 256>>>(Wo, wh, wl, nw4);
    gemm_bf16x3<0><<<gmma, 256, GEMM_SMEM>>>(xh, xl, wh, wl, bo, out, nullptr, nullptr);
}